// round 1
// baseline (speedup 1.0000x reference)
#include <cuda_runtime.h>
#include <math.h>

#define NTOK 8192
#define DIM  1024
#define NEXP 8
#define HID  1024
#define PMAX 8320          // max rows per expert list (8192+8 padded to 65*128)
#define CAPACITY 1280.0f

// ---------------- scratch (device globals; no allocation allowed) ----------------
__device__ int   g_topi[NTOK * 2];
__device__ float g_topw[NTOK * 2];
__device__ float g_corr[NEXP * 2];          // [row r][slot j] scatter-add sums
__device__ int   g_nent[NTOK];
__device__ int   g_cnt[NEXP];
__device__ int   g_ptok[NEXP * PMAX];
__device__ int   g_pslot[NEXP * PMAX];
__device__ float g_pw[NEXP * PMAX];
__device__ float g_y1[(size_t)NEXP * PMAX * HID];      // gelu(w*x@W1+b1), grouped per expert
__device__ float g_pout[(size_t)NTOK * 4 * DIM];       // per (token,slot) scaled outputs

// ---------------- router: logits, softmax, top-2 (normalized) ----------------
__global__ void router_kernel(const float* __restrict__ x,
                              const float* __restrict__ rw,
                              const float* __restrict__ rb) {
    const int n   = blockIdx.x;
    const int tid = threadIdx.x;              // 128 threads
    float acc[NEXP];
#pragma unroll
    for (int e = 0; e < NEXP; e++) acc[e] = 0.f;
    const float* xr = x + (size_t)n * DIM;
    for (int k = tid; k < DIM; k += 128) {
        float xv = xr[k];
        const float* r = rw + (size_t)k * NEXP;
#pragma unroll
        for (int e = 0; e < NEXP; e++) acc[e] += xv * r[e];
    }
    __shared__ float red[NEXP][128];
#pragma unroll
    for (int e = 0; e < NEXP; e++) red[e][tid] = acc[e];
    __syncthreads();
    if (tid < NEXP) {
        float s = 0.f;
        for (int i = 0; i < 128; i++) s += red[tid][i];   // fixed order: deterministic
        red[tid][0] = s + rb[tid];
    }
    __syncthreads();
    if (tid == 0) {
        float l[NEXP];
#pragma unroll
        for (int e = 0; e < NEXP; e++) l[e] = red[e][0];
        float m = l[0];
#pragma unroll
        for (int e = 1; e < NEXP; e++) m = fmaxf(m, l[e]);
        float p[NEXP], sum = 0.f;
#pragma unroll
        for (int e = 0; e < NEXP; e++) { p[e] = expf(l[e] - m); sum += p[e]; }
#pragma unroll
        for (int e = 0; e < NEXP; e++) p[e] /= sum;
        // top-2, ties -> lowest index first (strict >)
        int i0 = 0;
        for (int e = 1; e < NEXP; e++) if (p[e] > p[i0]) i0 = e;
        int i1 = (i0 == 0) ? 1 : 0;
        for (int e = 0; e < NEXP; e++) if (e != i0 && p[e] > p[i1]) i1 = e;
        float s2 = p[i0] + p[i1];
        g_topi[n * 2 + 0] = i0;
        g_topi[n * 2 + 1] = i1;
        g_topw[n * 2 + 0] = p[i0] / s2;
        g_topw[n * 2 + 1] = p[i1] / s2;
    }
}

// ---------------- scatter_add replication: corr[r][j] = sum_i top_p[i,j]*(top_i[i,j]==r) ----------------
__global__ void corr_kernel() {
    const int rj = blockIdx.x;                 // 16 blocks
    const int r = rj >> 1, j = rj & 1;
    const int tid = threadIdx.x;               // 256
    float acc = 0.f;
    for (int i = tid; i < NTOK; i += 256)
        if (g_topi[i * 2 + j] == r) acc += g_topw[i * 2 + j];
    __shared__ float s[256];
    s[tid] = acc;
    __syncthreads();
    for (int st = 128; st > 0; st >>= 1) {
        if (tid < st) s[tid] += s[tid + st];
        __syncthreads();
    }
    if (tid == 0) g_corr[rj] = s[0];
}

__global__ void zero_cnt_kernel() {
    if (threadIdx.x < NEXP) g_cnt[threadIdx.x] = 0;
}

// ---------------- build per-expert dispatch lists ----------------
__global__ void build_pairs_kernel() {
    const int n = blockIdx.x * blockDim.x + threadIdx.x;
    if (n >= NTOK) return;
    int   ee[4];
    float ww[4];
    int ne = 2;
    ee[0] = g_topi[n * 2 + 0]; ww[0] = g_topw[n * 2 + 0];
    ee[1] = g_topi[n * 2 + 1]; ww[1] = g_topw[n * 2 + 1];
    if (n < NEXP) {            // the buggy scatter_add touches rows 0..7, expert cols 0..1
#pragma unroll
        for (int j = 0; j < 2; j++) {
            float c = g_corr[n * 2 + j];
            int f = -1;
            for (int s = 0; s < ne; s++) if (ee[s] == j) f = s;
            if (f >= 0) ww[f] += c;
            else if (c != 0.0f) { ee[ne] = j; ww[ne] = c; ne++; }
        }
    }
    g_nent[n] = ne;
    for (int s = 0; s < ne; s++) {
        float w = fminf(ww[s], CAPACITY);
        int e = ee[s];
        int idx = atomicAdd(&g_cnt[e], 1);
        g_ptok[e * PMAX + idx]  = n;
        g_pslot[e * PMAX + idx] = s;
        g_pw[e * PMAX + idx]    = w;
    }
}

// ---------------- GEMM1: y1 = gelu(w * (x @ W1[e]) + b1[e]) ----------------
__global__ __launch_bounds__(256) void gemm1_kernel(const float* __restrict__ x,
                                                    const float* __restrict__ w1,
                                                    const float* __restrict__ b1) {
    const int e  = blockIdx.z;
    const int M  = g_cnt[e];
    const int m0 = blockIdx.y * 128;
    if (m0 >= M) return;
    const int n0  = blockIdx.x * 128;
    const int tid = threadIdx.x;
    const int tx = tid & 15, ty = tid >> 4;

    __shared__ float As[8][128];
    __shared__ float Bs[8][128];

    float acc[8][8];
#pragma unroll
    for (int i = 0; i < 8; i++)
#pragma unroll
        for (int j = 0; j < 8; j++) acc[i][j] = 0.f;

    const int aRow = tid >> 1;
    const int aK   = (tid & 1) * 4;
    int aTok = -1;
    if (m0 + aRow < M) aTok = g_ptok[e * PMAX + m0 + aRow];
    const int bK = tid >> 5;
    const int bN = (tid & 31) * 4;

    for (int k0 = 0; k0 < DIM; k0 += 8) {
        float4 av = make_float4(0.f, 0.f, 0.f, 0.f);
        if (aTok >= 0) av = *(const float4*)(x + (size_t)aTok * DIM + k0 + aK);
        float4 bv = *(const float4*)(w1 + ((size_t)(e * DIM + k0 + bK)) * HID + n0 + bN);
        __syncthreads();
        As[aK + 0][aRow] = av.x; As[aK + 1][aRow] = av.y;
        As[aK + 2][aRow] = av.z; As[aK + 3][aRow] = av.w;
        *(float4*)&Bs[bK][bN] = bv;
        __syncthreads();
#pragma unroll
        for (int k = 0; k < 8; k++) {
            float a[8], b[8];
            *(float4*)(a)     = *(const float4*)&As[k][ty * 8];
            *(float4*)(a + 4) = *(const float4*)&As[k][ty * 8 + 4];
            *(float4*)(b)     = *(const float4*)&Bs[k][tx * 8];
            *(float4*)(b + 4) = *(const float4*)&Bs[k][tx * 8 + 4];
#pragma unroll
            for (int i = 0; i < 8; i++)
#pragma unroll
                for (int j = 0; j < 8; j++) acc[i][j] += a[i] * b[j];
        }
    }

#pragma unroll
    for (int i = 0; i < 8; i++) {
        int r = m0 + ty * 8 + i;
        if (r >= M) break;
        float w = g_pw[e * PMAX + r];
        float* yrow = g_y1 + ((size_t)(e * PMAX + r)) * HID + n0 + tx * 8;
#pragma unroll
        for (int j = 0; j < 8; j++) {
            float v = w * acc[i][j] + b1[e * HID + n0 + tx * 8 + j];
            v = 0.5f * v * (1.0f + erff(v * 0.70710678118654752f));  // exact gelu
            yrow[j] = v;
        }
    }
}

// ---------------- GEMM2: pout = w * (y1 @ W2[e] + b2[e]) scattered to (token,slot) ----------------
__global__ __launch_bounds__(256) void gemm2_kernel(const float* __restrict__ w2,
                                                    const float* __restrict__ b2) {
    const int e  = blockIdx.z;
    const int M  = g_cnt[e];
    const int m0 = blockIdx.y * 128;
    if (m0 >= M) return;
    const int n0  = blockIdx.x * 128;
    const int tid = threadIdx.x;
    const int tx = tid & 15, ty = tid >> 4;

    __shared__ float As[8][128];
    __shared__ float Bs[8][128];

    float acc[8][8];
#pragma unroll
    for (int i = 0; i < 8; i++)
#pragma unroll
        for (int j = 0; j < 8; j++) acc[i][j] = 0.f;

    const int aRow = tid >> 1;
    const int aK   = (tid & 1) * 4;
    const bool aValid = (m0 + aRow < M);
    const float* Arow = g_y1 + ((size_t)(e * PMAX + m0 + aRow)) * HID;
    const int bK = tid >> 5;
    const int bN = (tid & 31) * 4;

    for (int k0 = 0; k0 < HID; k0 += 8) {
        float4 av = make_float4(0.f, 0.f, 0.f, 0.f);
        if (aValid) av = *(const float4*)(Arow + k0 + aK);
        float4 bv = *(const float4*)(w2 + ((size_t)(e * HID + k0 + bK)) * DIM + n0 + bN);
        __syncthreads();
        As[aK + 0][aRow] = av.x; As[aK + 1][aRow] = av.y;
        As[aK + 2][aRow] = av.z; As[aK + 3][aRow] = av.w;
        *(float4*)&Bs[bK][bN] = bv;
        __syncthreads();
#pragma unroll
        for (int k = 0; k < 8; k++) {
            float a[8], b[8];
            *(float4*)(a)     = *(const float4*)&As[k][ty * 8];
            *(float4*)(a + 4) = *(const float4*)&As[k][ty * 8 + 4];
            *(float4*)(b)     = *(const float4*)&Bs[k][tx * 8];
            *(float4*)(b + 4) = *(const float4*)&Bs[k][tx * 8 + 4];
#pragma unroll
            for (int i = 0; i < 8; i++)
#pragma unroll
                for (int j = 0; j < 8; j++) acc[i][j] += a[i] * b[j];
        }
    }

#pragma unroll
    for (int i = 0; i < 8; i++) {
        int r = m0 + ty * 8 + i;
        if (r >= M) break;
        int   tok  = g_ptok[e * PMAX + r];
        int   slot = g_pslot[e * PMAX + r];
        float w    = g_pw[e * PMAX + r];
        float* drow = g_pout + ((size_t)(tok * 4 + slot)) * DIM + n0 + tx * 8;
#pragma unroll
        for (int j = 0; j < 8; j++) {
            drow[j] = w * (acc[i][j] + b2[e * DIM + n0 + tx * 8 + j]);
        }
    }
}

// ---------------- combine: out[n] = sum over slots ----------------
__global__ void combine_kernel(float* __restrict__ out) {
    const int n   = blockIdx.x;
    const int tid = threadIdx.x;       // 256 -> 4 floats each
    const int ne  = g_nent[n];
    const int d   = tid * 4;
    float4 s = make_float4(0.f, 0.f, 0.f, 0.f);
    for (int sl = 0; sl < ne; sl++) {
        float4 v = *(const float4*)(g_pout + ((size_t)(n * 4 + sl)) * DIM + d);
        s.x += v.x; s.y += v.y; s.z += v.z; s.w += v.w;
    }
    *(float4*)(out + (size_t)n * DIM + d) = s;
}

// ---------------- launch ----------------
extern "C" void kernel_launch(void* const* d_in, const int* in_sizes, int n_in,
                              void* d_out, int out_size) {
    const float* x  = (const float*)d_in[0];
    const float* rw = (const float*)d_in[1];
    const float* rb = (const float*)d_in[2];
    const float* w1 = (const float*)d_in[3];
    const float* b1 = (const float*)d_in[4];
    const float* w2 = (const float*)d_in[5];
    const float* b2 = (const float*)d_in[6];
    float* out = (float*)d_out;

    router_kernel<<<NTOK, 128>>>(x, rw, rb);
    corr_kernel<<<16, 256>>>();
    zero_cnt_kernel<<<1, 32>>>();
    build_pairs_kernel<<<(NTOK + 255) / 256, 256>>>();

    dim3 gg(HID / 128, PMAX / 128, NEXP);   // (8, 65, 8); idle tiles early-exit
    gemm1_kernel<<<gg, 256>>>(x, w1, b1);
    gemm2_kernel<<<gg, 256>>>(w2, b2);
    combine_kernel<<<NTOK, 256>>>(out);
}

// round 4
// speedup vs baseline: 1.9571x; 1.9571x over previous
#include <cuda_runtime.h>
#include <cuda_bf16.h>
#include <math.h>
#include <stdint.h>

#define NTOK 8192
#define DIM  1024
#define NEXP 8
#define HID  1024
#define PMAX 8320
#define CAPACITY 1280.0f

#define KC     32            // K elements per pipeline stage
#define NCHUNK 32            // 1024 / 32
#define ROWB   80            // padded SMEM row stride in bytes (32 bf16 data + pad)
#define SPLIT_B (128 * ROWB)       // 10240 B: one 128x32 bf16 tile
#define STAGE_B (4 * SPLIT_B)      // Ah, Al, Bh, Bl
#define HDR     5120               // 512 src pointers (4KB) + 128 pred ints
#define SMEM_GEMM (HDR + 2 * STAGE_B)   // 87040

// ---------------- scratch globals ----------------
__device__ int   g_topi[NTOK * 2];
__device__ float g_topw[NTOK * 2];
__device__ float g_corr[NEXP * 2];
__device__ int   g_nent[NTOK];
__device__ int   g_cnt[NEXP];
__device__ int   g_ptok[NEXP * PMAX];
__device__ int   g_pslot[NEXP * PMAX];
__device__ float g_pw[NEXP * PMAX];
__device__ __align__(256) __nv_bfloat16 g_xh[(size_t)NTOK * DIM];
__device__ __align__(256) __nv_bfloat16 g_xl[(size_t)NTOK * DIM];
__device__ __align__(256) __nv_bfloat16 g_w1h[(size_t)NEXP * HID * DIM];   // [e][n][k]
__device__ __align__(256) __nv_bfloat16 g_w1l[(size_t)NEXP * HID * DIM];
__device__ __align__(256) __nv_bfloat16 g_w2h[(size_t)NEXP * DIM * HID];   // [e][n][k]
__device__ __align__(256) __nv_bfloat16 g_w2l[(size_t)NEXP * DIM * HID];
__device__ __align__(256) __nv_bfloat16 g_y1h[(size_t)NEXP * PMAX * HID];
__device__ __align__(256) __nv_bfloat16 g_y1l[(size_t)NEXP * PMAX * HID];
__device__ float g_pout[(size_t)NTOK * 4 * DIM];

// ---------------- small helpers ----------------
__device__ __forceinline__ void split2(float v, __nv_bfloat16& h, __nv_bfloat16& l) {
    h = __float2bfloat16(v);
    l = __float2bfloat16(v - __bfloat162float(h));
}
__device__ __forceinline__ uint32_t packbf2(__nv_bfloat16 a, __nv_bfloat16 b) {
    __nv_bfloat162 t = __halves2bfloat162(a, b);
    return *reinterpret_cast<uint32_t*>(&t);
}
__device__ __forceinline__ float gelu_f(float v) {
    return 0.5f * v * (1.0f + erff(v * 0.70710678118654752f));
}
__device__ __forceinline__ uint32_t smem_u32(const void* p) {
    uint32_t a;
    asm("{ .reg .u64 t; cvta.to.shared.u64 t, %1; cvt.u32.u64 %0, t; }" : "=r"(a) : "l"(p));
    return a;
}

#define LDSM_X4(r, addr) \
    asm volatile("ldmatrix.sync.aligned.m8n8.x4.shared.b16 {%0,%1,%2,%3}, [%4];" \
        : "=r"((r)[0]), "=r"((r)[1]), "=r"((r)[2]), "=r"((r)[3]) : "r"(addr))
#define LDSM_X2(r, addr) \
    asm volatile("ldmatrix.sync.aligned.m8n8.x2.shared.b16 {%0,%1}, [%2];" \
        : "=r"((r)[0]), "=r"((r)[1]) : "r"(addr))
#define MMA16816(c, a, b) \
    asm volatile("mma.sync.aligned.m16n8k16.row.col.f32.bf16.bf16.f32 " \
        "{%0,%1,%2,%3}, {%4,%5,%6,%7}, {%8,%9}, {%0,%1,%2,%3};" \
        : "+f"((c)[0]), "+f"((c)[1]), "+f"((c)[2]), "+f"((c)[3]) \
        : "r"((a)[0]), "r"((a)[1]), "r"((a)[2]), "r"((a)[3]), "r"((b)[0]), "r"((b)[1]))

// ---------------- prep: split x into bf16 hi/lo ----------------
__global__ void split_x_kernel(const float* __restrict__ x) {
    size_t i = ((size_t)blockIdx.x * 256 + threadIdx.x) * 4;
    float4 v = *(const float4*)(x + i);
    __nv_bfloat16 h0, l0, h1, l1, h2, l2, h3, l3;
    split2(v.x, h0, l0); split2(v.y, h1, l1); split2(v.z, h2, l2); split2(v.w, h3, l3);
    *(uint32_t*)(g_xh + i)     = packbf2(h0, h1);
    *(uint32_t*)(g_xh + i + 2) = packbf2(h2, h3);
    *(uint32_t*)(g_xl + i)     = packbf2(l0, l1);
    *(uint32_t*)(g_xl + i + 2) = packbf2(l2, l3);
}

// ---------------- prep: transpose+split weights  w[e][k][n] -> [e][n][k] hi/lo ----------------
__global__ void tsplit_kernel(const float* __restrict__ w, int which, int R, int C) {
    __shared__ float t[32][33];
    __nv_bfloat16* oh = which ? g_w2h : g_w1h;
    __nv_bfloat16* ol = which ? g_w2l : g_w1l;
    int e = blockIdx.z;
    int k0 = blockIdx.y * 32, n0 = blockIdx.x * 32;
    int tx = threadIdx.x, ty = threadIdx.y;
    const float* wp = w + (size_t)e * R * C;
#pragma unroll
    for (int r = 0; r < 32; r += 8)
        t[ty + r][tx] = wp[(size_t)(k0 + ty + r) * C + n0 + tx];
    __syncthreads();
#pragma unroll
    for (int r = 0; r < 32; r += 8) {
        float v = t[tx][ty + r];
        size_t o = ((size_t)e * C + n0 + ty + r) * R + k0 + tx;
        __nv_bfloat16 h, l; split2(v, h, l);
        oh[o] = h; ol[o] = l;
    }
}

// ---------------- router ----------------
__global__ void router_kernel(const float* __restrict__ x,
                              const float* __restrict__ rw,
                              const float* __restrict__ rb) {
    const int n = blockIdx.x, tid = threadIdx.x;
    float acc[NEXP];
#pragma unroll
    for (int e = 0; e < NEXP; e++) acc[e] = 0.f;
    const float* xr = x + (size_t)n * DIM;
    for (int k = tid; k < DIM; k += 128) {
        float xv = xr[k];
        const float* r = rw + (size_t)k * NEXP;
#pragma unroll
        for (int e = 0; e < NEXP; e++) acc[e] += xv * r[e];
    }
    __shared__ float red[NEXP][128];
#pragma unroll
    for (int e = 0; e < NEXP; e++) red[e][tid] = acc[e];
    __syncthreads();
    if (tid < NEXP) {
        float s = 0.f;
        for (int i = 0; i < 128; i++) s += red[tid][i];
        red[tid][0] = s + rb[tid];
    }
    __syncthreads();
    if (tid == 0) {
        float l[NEXP];
#pragma unroll
        for (int e = 0; e < NEXP; e++) l[e] = red[e][0];
        float m = l[0];
#pragma unroll
        for (int e = 1; e < NEXP; e++) m = fmaxf(m, l[e]);
        float p[NEXP], sum = 0.f;
#pragma unroll
        for (int e = 0; e < NEXP; e++) { p[e] = expf(l[e] - m); sum += p[e]; }
#pragma unroll
        for (int e = 0; e < NEXP; e++) p[e] /= sum;
        int i0 = 0;
        for (int e = 1; e < NEXP; e++) if (p[e] > p[i0]) i0 = e;
        int i1 = (i0 == 0) ? 1 : 0;
        for (int e = 0; e < NEXP; e++) if (e != i0 && p[e] > p[i1]) i1 = e;
        float s2 = p[i0] + p[i1];
        g_topi[n * 2 + 0] = i0;  g_topi[n * 2 + 1] = i1;
        g_topw[n * 2 + 0] = p[i0] / s2;  g_topw[n * 2 + 1] = p[i1] / s2;
    }
}

__global__ void corr_kernel() {
    const int rj = blockIdx.x, r = rj >> 1, j = rj & 1, tid = threadIdx.x;
    float acc = 0.f;
    for (int i = tid; i < NTOK; i += 256)
        if (g_topi[i * 2 + j] == r) acc += g_topw[i * 2 + j];
    __shared__ float s[256];
    s[tid] = acc; __syncthreads();
    for (int st = 128; st > 0; st >>= 1) { if (tid < st) s[tid] += s[tid + st]; __syncthreads(); }
    if (tid == 0) g_corr[rj] = s[0];
}

__global__ void zero_cnt_kernel() { if (threadIdx.x < NEXP) g_cnt[threadIdx.x] = 0; }

__global__ void build_pairs_kernel() {
    const int n = blockIdx.x * blockDim.x + threadIdx.x;
    if (n >= NTOK) return;
    int ee[4]; float ww[4]; int ne = 2;
    ee[0] = g_topi[n * 2 + 0]; ww[0] = g_topw[n * 2 + 0];
    ee[1] = g_topi[n * 2 + 1]; ww[1] = g_topw[n * 2 + 1];
    if (n < NEXP) {
#pragma unroll
        for (int j = 0; j < 2; j++) {
            float c = g_corr[n * 2 + j];
            int f = -1;
            for (int s = 0; s < ne; s++) if (ee[s] == j) f = s;
            if (f >= 0) ww[f] += c;
            else if (c != 0.0f) { ee[ne] = j; ww[ne] = c; ne++; }
        }
    }
    g_nent[n] = ne;
    for (int s = 0; s < ne; s++) {
        float w = fminf(ww[s], CAPACITY);
        int e = ee[s];
        int idx = atomicAdd(&g_cnt[e], 1);
        g_ptok[e * PMAX + idx] = n;
        g_pslot[e * PMAX + idx] = s;
        g_pw[e * PMAX + idx] = w;
    }
}

// ---------------- GEMM mainloop (shared by both GEMMs) ----------------
__device__ __forceinline__ void load_stage(char* smem, uint32_t sb, int tid, int c) {
    const __nv_bfloat16* const* s_ptr = (const __nv_bfloat16* const*)smem;   // 512 entries
    const int* s_pred = (const int*)(smem + 4096);                            // 128 entries
    const int kel = c * KC;
#pragma unroll
    for (int it = 0; it < 8; it++) {
        const int id = tid + it * 256;
        const int region = id >> 9, within = id & 511;
        const int row = within >> 2, seg = within & 3;
        const char* src = (const char*)(s_ptr[region * 128 + row] + kel) + seg * 16;
        uint32_t dst = sb + HDR + (uint32_t)((c & 1) * STAGE_B + region * SPLIT_B + row * ROWB + seg * 16);
        int sz = (region < 2) ? s_pred[row] : 16;
        asm volatile("cp.async.cg.shared.global [%0], [%1], 16, %2;"
                     :: "r"(dst), "l"(src), "r"(sz) : "memory");
    }
    asm volatile("cp.async.commit_group;" ::: "memory");
}

__device__ __forceinline__ void compute_stage(uint32_t sb, int tid, int buf, float acc[4][4][4]) {
    const int lane = tid & 31, wid = tid >> 5;
    const int wr = wid >> 2, wc = wid & 3;
    const uint32_t base = sb + HDR + (uint32_t)(buf * STAGE_B);
    const int arow = wr * 64 + (lane & 15);
    const int acol = (lane >> 4) * 8;                 // k offset 0/8
    const int brow = wc * 32 + (lane & 7);
    const int bcol = ((lane >> 3) & 1) * 8;           // k offset 0/8
#pragma unroll
    for (int kst = 0; kst < 2; kst++) {
        const uint32_t abase = base + (uint32_t)(arow * ROWB + (kst * 16 + acol) * 2);
        const uint32_t bbase = base + (uint32_t)(2 * SPLIT_B + brow * ROWB + (kst * 16 + bcol) * 2);
        uint32_t ah[4][4], al[4][4], bh[4][2], bl[4][2];
#pragma unroll
        for (int mt = 0; mt < 4; mt++) {
            LDSM_X4(ah[mt], abase + mt * 16 * ROWB);
            LDSM_X4(al[mt], abase + SPLIT_B + mt * 16 * ROWB);
        }
#pragma unroll
        for (int nt = 0; nt < 4; nt++) {
            LDSM_X2(bh[nt], bbase + nt * 8 * ROWB);
            LDSM_X2(bl[nt], bbase + SPLIT_B + nt * 8 * ROWB);
        }
#pragma unroll
        for (int mt = 0; mt < 4; mt++)
#pragma unroll
            for (int nt = 0; nt < 4; nt++) {
                MMA16816(acc[mt][nt], ah[mt], bh[nt]);
                MMA16816(acc[mt][nt], ah[mt], bl[nt]);
                MMA16816(acc[mt][nt], al[mt], bh[nt]);
            }
    }
}

__device__ __forceinline__ void gemm_mainloop(char* smem, uint32_t sb, int tid, float acc[4][4][4]) {
#pragma unroll
    for (int mt = 0; mt < 4; mt++)
#pragma unroll
        for (int nt = 0; nt < 4; nt++)
#pragma unroll
            for (int i = 0; i < 4; i++) acc[mt][nt][i] = 0.f;
    load_stage(smem, sb, tid, 0);
#pragma unroll 1
    for (int c = 0; c < NCHUNK; c++) {
        if (c + 1 < NCHUNK) {
            load_stage(smem, sb, tid, c + 1);
            asm volatile("cp.async.wait_group 1;" ::: "memory");
        } else {
            asm volatile("cp.async.wait_group 0;" ::: "memory");
        }
        __syncthreads();
        compute_stage(sb, tid, c & 1, acc);
        __syncthreads();
    }
}

// ---------------- GEMM1: y1 = gelu(w * (x @ W1) + b1) -> bf16 hi/lo ----------------
__global__ __launch_bounds__(256, 1) void gemm1_tc(const float* __restrict__ b1) {
    const int e = blockIdx.z;
    const int M = g_cnt[e];
    const int m0 = blockIdx.y * 128;
    if (m0 >= M) return;
    const int n0 = blockIdx.x * 128;
    extern __shared__ char smem[];
    const uint32_t sb = smem_u32(smem);
    const int tid = threadIdx.x;

    {
        const __nv_bfloat16** s_ptr = (const __nv_bfloat16**)smem;
        int* s_pred = (int*)(smem + 4096);
        if (tid < 128) {
            int p = m0 + tid;
            bool v = p < M;
            int tok = v ? g_ptok[e * PMAX + p] : 0;
            s_ptr[0 * 128 + tid] = g_xh + (size_t)tok * DIM;
            s_ptr[1 * 128 + tid] = g_xl + (size_t)tok * DIM;
            s_ptr[2 * 128 + tid] = g_w1h + ((size_t)e * HID + n0 + tid) * DIM;
            s_ptr[3 * 128 + tid] = g_w1l + ((size_t)e * HID + n0 + tid) * DIM;
            s_pred[tid] = v ? 16 : 0;
        }
    }
    __syncthreads();

    float acc[4][4][4];
    gemm_mainloop(smem, sb, tid, acc);

    const int lane = tid & 31, wid = tid >> 5;
    const int wr = wid >> 2, wc = wid & 3;
    const int gid = lane >> 2, tig = lane & 3;
    const float* b1e = b1 + e * HID + n0 + wc * 32;
#pragma unroll
    for (int mt = 0; mt < 4; mt++) {
        const int p0 = m0 + wr * 64 + mt * 16 + gid;
        const int p1 = p0 + 8;
        const bool v0 = p0 < M, v1 = p1 < M;
        const float w0 = v0 ? g_pw[e * PMAX + p0] : 0.f;
        const float w1 = v1 ? g_pw[e * PMAX + p1] : 0.f;
        __nv_bfloat16* oh0 = g_y1h + ((size_t)(e * PMAX + p0)) * HID + n0 + wc * 32;
        __nv_bfloat16* ol0 = g_y1l + ((size_t)(e * PMAX + p0)) * HID + n0 + wc * 32;
        __nv_bfloat16* oh1 = g_y1h + ((size_t)(e * PMAX + p1)) * HID + n0 + wc * 32;
        __nv_bfloat16* ol1 = g_y1l + ((size_t)(e * PMAX + p1)) * HID + n0 + wc * 32;
#pragma unroll
        for (int nt = 0; nt < 4; nt++) {
            const int co = nt * 8 + 2 * tig;
            const float* c = acc[mt][nt];
            if (v0) {
                float t0 = gelu_f(w0 * c[0] + b1e[co]);
                float t1 = gelu_f(w0 * c[1] + b1e[co + 1]);
                __nv_bfloat16 h0, l0, h1, l1;
                split2(t0, h0, l0); split2(t1, h1, l1);
                *(uint32_t*)(oh0 + co) = packbf2(h0, h1);
                *(uint32_t*)(ol0 + co) = packbf2(l0, l1);
            }
            if (v1) {
                float t0 = gelu_f(w1 * c[2] + b1e[co]);
                float t1 = gelu_f(w1 * c[3] + b1e[co + 1]);
                __nv_bfloat16 h0, l0, h1, l1;
                split2(t0, h0, l0); split2(t1, h1, l1);
                *(uint32_t*)(oh1 + co) = packbf2(h0, h1);
                *(uint32_t*)(ol1 + co) = packbf2(l0, l1);
            }
        }
    }
}

// ---------------- GEMM2: pout = w * (y1 @ W2 + b2) ----------------
__global__ __launch_bounds__(256, 1) void gemm2_tc(const float* __restrict__ b2) {
    const int e = blockIdx.z;
    const int M = g_cnt[e];
    const int m0 = blockIdx.y * 128;
    if (m0 >= M) return;
    const int n0 = blockIdx.x * 128;
    extern __shared__ char smem[];
    const uint32_t sb = smem_u32(smem);
    const int tid = threadIdx.x;

    {
        const __nv_bfloat16** s_ptr = (const __nv_bfloat16**)smem;
        int* s_pred = (int*)(smem + 4096);
        if (tid < 128) {
            int p = m0 + tid;
            bool v = p < M;
            size_t ar = ((size_t)(e * PMAX + (v ? p : 0))) * HID;
            s_ptr[0 * 128 + tid] = g_y1h + ar;
            s_ptr[1 * 128 + tid] = g_y1l + ar;
            s_ptr[2 * 128 + tid] = g_w2h + ((size_t)e * DIM + n0 + tid) * HID;
            s_ptr[3 * 128 + tid] = g_w2l + ((size_t)e * DIM + n0 + tid) * HID;
            s_pred[tid] = v ? 16 : 0;
        }
    }
    __syncthreads();

    float acc[4][4][4];
    gemm_mainloop(smem, sb, tid, acc);

    const int lane = tid & 31, wid = tid >> 5;
    const int wr = wid >> 2, wc = wid & 3;
    const int gid = lane >> 2, tig = lane & 3;
    const float* b2e = b2 + e * DIM + n0 + wc * 32;
#pragma unroll
    for (int mt = 0; mt < 4; mt++) {
        const int p0 = m0 + wr * 64 + mt * 16 + gid;
        const int p1 = p0 + 8;
        const bool v0 = p0 < M, v1 = p1 < M;
        int tok0 = 0, slot0 = 0, tok1 = 0, slot1 = 0;
        float w0 = 0.f, w1 = 0.f;
        if (v0) { tok0 = g_ptok[e * PMAX + p0]; slot0 = g_pslot[e * PMAX + p0]; w0 = g_pw[e * PMAX + p0]; }
        if (v1) { tok1 = g_ptok[e * PMAX + p1]; slot1 = g_pslot[e * PMAX + p1]; w1 = g_pw[e * PMAX + p1]; }
        float* d0 = g_pout + ((size_t)(tok0 * 4 + slot0)) * DIM + n0 + wc * 32;
        float* d1 = g_pout + ((size_t)(tok1 * 4 + slot1)) * DIM + n0 + wc * 32;
#pragma unroll
        for (int nt = 0; nt < 4; nt++) {
            const int co = nt * 8 + 2 * tig;
            const float* c = acc[mt][nt];
            if (v0) *(float2*)(d0 + co) = make_float2(w0 * (c[0] + b2e[co]), w0 * (c[1] + b2e[co + 1]));
            if (v1) *(float2*)(d1 + co) = make_float2(w1 * (c[2] + b2e[co]), w1 * (c[3] + b2e[co + 1]));
        }
    }
}

// ---------------- combine ----------------
__global__ void combine_kernel(float* __restrict__ out) {
    const int n = blockIdx.x, tid = threadIdx.x;
    const int ne = g_nent[n];
    const int d = tid * 4;
    float4 s = make_float4(0.f, 0.f, 0.f, 0.f);
    for (int sl = 0; sl < ne; sl++) {
        float4 v = *(const float4*)(g_pout + ((size_t)(n * 4 + sl)) * DIM + d);
        s.x += v.x; s.y += v.y; s.z += v.z; s.w += v.w;
    }
    *(float4*)(out + (size_t)n * DIM + d) = s;
}

// ---------------- launch ----------------
extern "C" void kernel_launch(void* const* d_in, const int* in_sizes, int n_in,
                              void* d_out, int out_size) {
    const float* x  = (const float*)d_in[0];
    const float* rw = (const float*)d_in[1];
    const float* rb = (const float*)d_in[2];
    const float* w1 = (const float*)d_in[3];
    const float* b1 = (const float*)d_in[4];
    const float* w2 = (const float*)d_in[5];
    const float* b2 = (const float*)d_in[6];
    float* out = (float*)d_out;

    cudaFuncSetAttribute(gemm1_tc, cudaFuncAttributeMaxDynamicSharedMemorySize, SMEM_GEMM);
    cudaFuncSetAttribute(gemm2_tc, cudaFuncAttributeMaxDynamicSharedMemorySize, SMEM_GEMM);

    split_x_kernel<<<(NTOK * DIM) / 1024, 256>>>(x);
    {
        dim3 tg(DIM / 32, HID / 32, NEXP);
        tsplit_kernel<<<tg, dim3(32, 8)>>>(w1, 0, DIM, HID);
        tsplit_kernel<<<tg, dim3(32, 8)>>>(w2, 1, HID, DIM);
    }

    router_kernel<<<NTOK, 128>>>(x, rw, rb);
    corr_kernel<<<16, 256>>>();
    zero_cnt_kernel<<<1, 32>>>();
    build_pairs_kernel<<<(NTOK + 255) / 256, 256>>>();

    dim3 gg(HID / 128, PMAX / 128, NEXP);    // (8, 65, 8); dead tiles exit at top
    gemm1_tc<<<gg, 256, SMEM_GEMM>>>(b1);
    gemm2_tc<<<gg, 256, SMEM_GEMM>>>(b2);
    combine_kernel<<<NTOK, 256>>>(out);
}

// round 5
// speedup vs baseline: 2.3606x; 1.2062x over previous
#include <cuda_runtime.h>
#include <cuda_bf16.h>
#include <math.h>
#include <stdint.h>

#define NTOK 8192
#define DIM  1024
#define NEXP 8
#define HID  1024
#define PMAX 8320
#define CAPACITY 1280.0f

#define KC     64            // K elements per pipeline stage
#define NCHUNK 16            // 1024 / 64
#define NSTAGE 3
#define ROWB   144           // 128B data + 16B pad
#define SPLIT_B (128 * ROWB)       // 18432 B: one 128x64 bf16 tile
#define STAGE_B (4 * SPLIT_B)      // Ah, Al, Bh, Bl = 73728
#define HDR     5120               // 512 src pointers (4KB) + 128 pred ints
#define SMEM_GEMM (HDR + NSTAGE * STAGE_B)   // 226304

// ---------------- scratch globals ----------------
__device__ int   g_topi[NTOK * 2];
__device__ float g_topw[NTOK * 2];
__device__ float g_corr[NEXP * 2];
__device__ int   g_nent[NTOK];
__device__ int   g_cnt[NEXP];
__device__ int   g_ptok[NEXP * PMAX];
__device__ int   g_pslot[NEXP * PMAX];
__device__ float g_pw[NEXP * PMAX];
__device__ __align__(256) __nv_bfloat16 g_xh[(size_t)NTOK * DIM];
__device__ __align__(256) __nv_bfloat16 g_xl[(size_t)NTOK * DIM];
__device__ __align__(256) __nv_bfloat16 g_w1h[(size_t)NEXP * HID * DIM];   // [e][n][k]
__device__ __align__(256) __nv_bfloat16 g_w1l[(size_t)NEXP * HID * DIM];
__device__ __align__(256) __nv_bfloat16 g_w2h[(size_t)NEXP * DIM * HID];   // [e][n][k]
__device__ __align__(256) __nv_bfloat16 g_w2l[(size_t)NEXP * DIM * HID];
__device__ __align__(256) __nv_bfloat16 g_y1h[(size_t)NEXP * PMAX * HID];
__device__ __align__(256) __nv_bfloat16 g_y1l[(size_t)NEXP * PMAX * HID];
__device__ float g_pout[(size_t)NTOK * 4 * DIM];

// ---------------- small helpers ----------------
__device__ __forceinline__ void split2(float v, __nv_bfloat16& h, __nv_bfloat16& l) {
    h = __float2bfloat16(v);
    l = __float2bfloat16(v - __bfloat162float(h));
}
__device__ __forceinline__ uint32_t packbf2(__nv_bfloat16 a, __nv_bfloat16 b) {
    __nv_bfloat162 t = __halves2bfloat162(a, b);
    return *reinterpret_cast<uint32_t*>(&t);
}
__device__ __forceinline__ float gelu_f(float v) {
    return 0.5f * v * (1.0f + erff(v * 0.70710678118654752f));
}
__device__ __forceinline__ uint32_t smem_u32(const void* p) {
    uint32_t a;
    asm("{ .reg .u64 t; cvta.to.shared.u64 t, %1; cvt.u32.u64 %0, t; }" : "=r"(a) : "l"(p));
    return a;
}

#define LDSM_X4(r, addr) \
    asm volatile("ldmatrix.sync.aligned.m8n8.x4.shared.b16 {%0,%1,%2,%3}, [%4];" \
        : "=r"((r)[0]), "=r"((r)[1]), "=r"((r)[2]), "=r"((r)[3]) : "r"(addr))
#define LDSM_X2(r, addr) \
    asm volatile("ldmatrix.sync.aligned.m8n8.x2.shared.b16 {%0,%1}, [%2];" \
        : "=r"((r)[0]), "=r"((r)[1]) : "r"(addr))
#define MMA16816(c, a, b) \
    asm volatile("mma.sync.aligned.m16n8k16.row.col.f32.bf16.bf16.f32 " \
        "{%0,%1,%2,%3}, {%4,%5,%6,%7}, {%8,%9}, {%0,%1,%2,%3};" \
        : "+f"((c)[0]), "+f"((c)[1]), "+f"((c)[2]), "+f"((c)[3]) \
        : "r"((a)[0]), "r"((a)[1]), "r"((a)[2]), "r"((a)[3]), "r"((b)[0]), "r"((b)[1]))

// ---------------- fused router + x split ----------------
// 8 warps/block, one token per warp; rw staged in padded smem.
__global__ __launch_bounds__(256) void router_split_kernel(
        const float* __restrict__ x,
        const float* __restrict__ rw,
        const float* __restrict__ rb) {
    __shared__ float s_rw[DIM * 9];          // [k*9 + e], pad 9 -> few conflicts
    const int tid = threadIdx.x, lane = tid & 31, wid = tid >> 5;
    for (int i = tid; i < DIM * NEXP; i += 256) {
        int k = i >> 3, e = i & 7;
        s_rw[k * 9 + e] = rw[i];
    }
    __syncthreads();

    const int n = blockIdx.x * 8 + wid;
    const float* xr = x + (size_t)n * DIM;
    float acc[NEXP];
#pragma unroll
    for (int e = 0; e < NEXP; e++) acc[e] = 0.f;

#pragma unroll 4
    for (int i = 0; i < 16; i++) {
        const int k = i * 64 + lane * 2;
        float2 v = *(const float2*)(xr + k);
        __nv_bfloat16 h0, l0, h1, l1;
        split2(v.x, h0, l0); split2(v.y, h1, l1);
        *(uint32_t*)(g_xh + (size_t)n * DIM + k) = packbf2(h0, h1);
        *(uint32_t*)(g_xl + (size_t)n * DIM + k) = packbf2(l0, l1);
        const float* r0 = s_rw + k * 9;
        const float* r1 = s_rw + (k + 1) * 9;
#pragma unroll
        for (int e = 0; e < NEXP; e++) acc[e] += v.x * r0[e] + v.y * r1[e];
    }
    // fixed-order butterfly reduce (deterministic)
#pragma unroll
    for (int off = 16; off > 0; off >>= 1)
#pragma unroll
        for (int e = 0; e < NEXP; e++)
            acc[e] += __shfl_xor_sync(0xFFFFFFFFu, acc[e], off);

    if (lane == 0) {
        float l[NEXP];
#pragma unroll
        for (int e = 0; e < NEXP; e++) l[e] = acc[e] + rb[e];
        float m = l[0];
#pragma unroll
        for (int e = 1; e < NEXP; e++) m = fmaxf(m, l[e]);
        float p[NEXP], sum = 0.f;
#pragma unroll
        for (int e = 0; e < NEXP; e++) { p[e] = expf(l[e] - m); sum += p[e]; }
#pragma unroll
        for (int e = 0; e < NEXP; e++) p[e] /= sum;
        int i0 = 0;
        for (int e = 1; e < NEXP; e++) if (p[e] > p[i0]) i0 = e;
        int i1 = (i0 == 0) ? 1 : 0;
        for (int e = 0; e < NEXP; e++) if (e != i0 && p[e] > p[i1]) i1 = e;
        float s2 = p[i0] + p[i1];
        g_topi[n * 2 + 0] = i0;  g_topi[n * 2 + 1] = i1;
        g_topw[n * 2 + 0] = p[i0] / s2;  g_topw[n * 2 + 1] = p[i1] / s2;
    }
}

// ---------------- prep: transpose+split weights  w[e][k][n] -> [e][n][k] hi/lo ----------------
__global__ void tsplit_kernel(const float* __restrict__ w, int which, int R, int C) {
    __shared__ float t[32][33];
    __nv_bfloat16* oh = which ? g_w2h : g_w1h;
    __nv_bfloat16* ol = which ? g_w2l : g_w1l;
    int e = blockIdx.z;
    int k0 = blockIdx.y * 32, n0 = blockIdx.x * 32;
    int tx = threadIdx.x, ty = threadIdx.y;
    const float* wp = w + (size_t)e * R * C;
#pragma unroll
    for (int r = 0; r < 32; r += 8)
        t[ty + r][tx] = wp[(size_t)(k0 + ty + r) * C + n0 + tx];
    __syncthreads();
#pragma unroll
    for (int r = 0; r < 32; r += 8) {
        float v = t[tx][ty + r];
        size_t o = ((size_t)e * C + n0 + ty + r) * R + k0 + tx;
        __nv_bfloat16 h, l; split2(v, h, l);
        oh[o] = h; ol[o] = l;
    }
}

__global__ void corr_kernel() {
    const int rj = blockIdx.x, r = rj >> 1, j = rj & 1, tid = threadIdx.x;
    float acc = 0.f;
    for (int i = tid; i < NTOK; i += 256)
        if (g_topi[i * 2 + j] == r) acc += g_topw[i * 2 + j];
    __shared__ float s[256];
    s[tid] = acc; __syncthreads();
    for (int st = 128; st > 0; st >>= 1) { if (tid < st) s[tid] += s[tid + st]; __syncthreads(); }
    if (tid == 0) g_corr[rj] = s[0];
}

__global__ void zero_cnt_kernel() { if (threadIdx.x < NEXP) g_cnt[threadIdx.x] = 0; }

__global__ void build_pairs_kernel() {
    const int n = blockIdx.x * blockDim.x + threadIdx.x;
    if (n >= NTOK) return;
    int ee[4]; float ww[4]; int ne = 2;
    ee[0] = g_topi[n * 2 + 0]; ww[0] = g_topw[n * 2 + 0];
    ee[1] = g_topi[n * 2 + 1]; ww[1] = g_topw[n * 2 + 1];
    if (n < NEXP) {
#pragma unroll
        for (int j = 0; j < 2; j++) {
            float c = g_corr[n * 2 + j];
            int f = -1;
            for (int s = 0; s < ne; s++) if (ee[s] == j) f = s;
            if (f >= 0) ww[f] += c;
            else if (c != 0.0f) { ee[ne] = j; ww[ne] = c; ne++; }
        }
    }
    g_nent[n] = ne;
    for (int s = 0; s < ne; s++) {
        float w = fminf(ww[s], CAPACITY);
        int e = ee[s];
        int idx = atomicAdd(&g_cnt[e], 1);
        g_ptok[e * PMAX + idx] = n;
        g_pslot[e * PMAX + idx] = s;
        g_pw[e * PMAX + idx] = w;
    }
}

// ---------------- GEMM mainloop (shared by both GEMMs) ----------------
__device__ __forceinline__ void load_stage(char* smem, uint32_t sb, int tid, int c) {
    const __nv_bfloat16* const* s_ptr = (const __nv_bfloat16* const*)smem;   // 512 entries
    const int* s_pred = (const int*)(smem + 4096);                            // 128 entries
    const int kel = c * KC;
    const uint32_t sbase = sb + HDR + (uint32_t)((c % NSTAGE) * STAGE_B);
#pragma unroll
    for (int it = 0; it < 16; it++) {
        const int id = tid + it * 256;
        const int region = id >> 10, within = id & 1023;
        const int row = within >> 3, seg = within & 7;
        const char* src = (const char*)(s_ptr[region * 128 + row] + kel) + seg * 16;
        uint32_t dst = sbase + (uint32_t)(region * SPLIT_B + row * ROWB + seg * 16);
        int sz = (region < 2) ? s_pred[row] : 16;
        asm volatile("cp.async.cg.shared.global [%0], [%1], 16, %2;"
                     :: "r"(dst), "l"(src), "r"(sz) : "memory");
    }
    asm volatile("cp.async.commit_group;" ::: "memory");
}

__device__ __forceinline__ void compute_stage(uint32_t sb, int tid, int buf, float acc[4][4][4]) {
    const int lane = tid & 31, wid = tid >> 5;
    const int wr = wid >> 2, wc = wid & 3;
    const uint32_t base = sb + HDR + (uint32_t)(buf * STAGE_B);
    const int arow = wr * 64 + (lane & 15);
    const int acol = (lane >> 4) * 8;                 // k offset 0/8
    const int brow = wc * 32 + (lane & 7);
    const int bcol = ((lane >> 3) & 1) * 8;           // k offset 0/8
#pragma unroll
    for (int kst = 0; kst < 4; kst++) {
        const uint32_t abase = base + (uint32_t)(arow * ROWB + (kst * 16 + acol) * 2);
        const uint32_t bbase = base + (uint32_t)(2 * SPLIT_B + brow * ROWB + (kst * 16 + bcol) * 2);
        uint32_t ah[4][4], al[4][4], bh[4][2], bl[4][2];
#pragma unroll
        for (int mt = 0; mt < 4; mt++) {
            LDSM_X4(ah[mt], abase + mt * 16 * ROWB);
            LDSM_X4(al[mt], abase + SPLIT_B + mt * 16 * ROWB);
        }
#pragma unroll
        for (int nt = 0; nt < 4; nt++) {
            LDSM_X2(bh[nt], bbase + nt * 8 * ROWB);
            LDSM_X2(bl[nt], bbase + SPLIT_B + nt * 8 * ROWB);
        }
#pragma unroll
        for (int mt = 0; mt < 4; mt++)
#pragma unroll
            for (int nt = 0; nt < 4; nt++) {
                MMA16816(acc[mt][nt], ah[mt], bh[nt]);
                MMA16816(acc[mt][nt], ah[mt], bl[nt]);
                MMA16816(acc[mt][nt], al[mt], bh[nt]);
            }
    }
}

__device__ __forceinline__ void gemm_mainloop(char* smem, uint32_t sb, int tid, float acc[4][4][4]) {
#pragma unroll
    for (int mt = 0; mt < 4; mt++)
#pragma unroll
        for (int nt = 0; nt < 4; nt++)
#pragma unroll
            for (int i = 0; i < 4; i++) acc[mt][nt][i] = 0.f;
    load_stage(smem, sb, tid, 0);
    load_stage(smem, sb, tid, 1);
    load_stage(smem, sb, tid, 2);
#pragma unroll 1
    for (int c = 0; c < NCHUNK; c++) {
        // pending groups entering iter c: min(3, NCHUNK-c); want stage c drained
        if (c <= NCHUNK - 3)      asm volatile("cp.async.wait_group 2;" ::: "memory");
        else if (c == NCHUNK - 2) asm volatile("cp.async.wait_group 1;" ::: "memory");
        else                      asm volatile("cp.async.wait_group 0;" ::: "memory");
        __syncthreads();
        compute_stage(sb, tid, c % NSTAGE, acc);
        __syncthreads();
        if (c + 3 < NCHUNK) load_stage(smem, sb, tid, c + 3);
    }
}

// ---------------- GEMM1: y1 = gelu(w * (x @ W1) + b1) -> bf16 hi/lo ----------------
__global__ __launch_bounds__(256, 1) void gemm1_tc(const float* __restrict__ b1) {
    const int e = blockIdx.z;
    const int M = g_cnt[e];
    const int m0 = blockIdx.y * 128;
    if (m0 >= M) return;
    const int n0 = blockIdx.x * 128;
    extern __shared__ char smem[];
    const uint32_t sb = smem_u32(smem);
    const int tid = threadIdx.x;

    {
        const __nv_bfloat16** s_ptr = (const __nv_bfloat16**)smem;
        int* s_pred = (int*)(smem + 4096);
        if (tid < 128) {
            int p = m0 + tid;
            bool v = p < M;
            int tok = v ? g_ptok[e * PMAX + p] : 0;
            s_ptr[0 * 128 + tid] = g_xh + (size_t)tok * DIM;
            s_ptr[1 * 128 + tid] = g_xl + (size_t)tok * DIM;
            s_ptr[2 * 128 + tid] = g_w1h + ((size_t)e * HID + n0 + tid) * DIM;
            s_ptr[3 * 128 + tid] = g_w1l + ((size_t)e * HID + n0 + tid) * DIM;
            s_pred[tid] = v ? 16 : 0;
        }
    }
    __syncthreads();

    float acc[4][4][4];
    gemm_mainloop(smem, sb, tid, acc);

    const int lane = tid & 31, wid = tid >> 5;
    const int wr = wid >> 2, wc = wid & 3;
    const int gid = lane >> 2, tig = lane & 3;
    const float* b1e = b1 + e * HID + n0 + wc * 32;
#pragma unroll
    for (int mt = 0; mt < 4; mt++) {
        const int p0 = m0 + wr * 64 + mt * 16 + gid;
        const int p1 = p0 + 8;
        const bool v0 = p0 < M, v1 = p1 < M;
        const float w0 = v0 ? g_pw[e * PMAX + p0] : 0.f;
        const float w1 = v1 ? g_pw[e * PMAX + p1] : 0.f;
        __nv_bfloat16* oh0 = g_y1h + ((size_t)(e * PMAX + p0)) * HID + n0 + wc * 32;
        __nv_bfloat16* ol0 = g_y1l + ((size_t)(e * PMAX + p0)) * HID + n0 + wc * 32;
        __nv_bfloat16* oh1 = g_y1h + ((size_t)(e * PMAX + p1)) * HID + n0 + wc * 32;
        __nv_bfloat16* ol1 = g_y1l + ((size_t)(e * PMAX + p1)) * HID + n0 + wc * 32;
#pragma unroll
        for (int nt = 0; nt < 4; nt++) {
            const int co = nt * 8 + 2 * tig;
            const float* c = acc[mt][nt];
            if (v0) {
                float t0 = gelu_f(w0 * c[0] + b1e[co]);
                float t1 = gelu_f(w0 * c[1] + b1e[co + 1]);
                __nv_bfloat16 h0, l0, h1, l1;
                split2(t0, h0, l0); split2(t1, h1, l1);
                *(uint32_t*)(oh0 + co) = packbf2(h0, h1);
                *(uint32_t*)(ol0 + co) = packbf2(l0, l1);
            }
            if (v1) {
                float t0 = gelu_f(w1 * c[2] + b1e[co]);
                float t1 = gelu_f(w1 * c[3] + b1e[co + 1]);
                __nv_bfloat16 h0, l0, h1, l1;
                split2(t0, h0, l0); split2(t1, h1, l1);
                *(uint32_t*)(oh1 + co) = packbf2(h0, h1);
                *(uint32_t*)(ol1 + co) = packbf2(l0, l1);
            }
        }
    }
}

// ---------------- GEMM2: pout = w * (y1 @ W2 + b2) ----------------
__global__ __launch_bounds__(256, 1) void gemm2_tc(const float* __restrict__ b2) {
    const int e = blockIdx.z;
    const int M = g_cnt[e];
    const int m0 = blockIdx.y * 128;
    if (m0 >= M) return;
    const int n0 = blockIdx.x * 128;
    extern __shared__ char smem[];
    const uint32_t sb = smem_u32(smem);
    const int tid = threadIdx.x;

    {
        const __nv_bfloat16** s_ptr = (const __nv_bfloat16**)smem;
        int* s_pred = (int*)(smem + 4096);
        if (tid < 128) {
            int p = m0 + tid;
            bool v = p < M;
            size_t ar = ((size_t)(e * PMAX + (v ? p : 0))) * HID;
            s_ptr[0 * 128 + tid] = g_y1h + ar;
            s_ptr[1 * 128 + tid] = g_y1l + ar;
            s_ptr[2 * 128 + tid] = g_w2h + ((size_t)e * DIM + n0 + tid) * HID;
            s_ptr[3 * 128 + tid] = g_w2l + ((size_t)e * DIM + n0 + tid) * HID;
            s_pred[tid] = v ? 16 : 0;
        }
    }
    __syncthreads();

    float acc[4][4][4];
    gemm_mainloop(smem, sb, tid, acc);

    const int lane = tid & 31, wid = tid >> 5;
    const int wr = wid >> 2, wc = wid & 3;
    const int gid = lane >> 2, tig = lane & 3;
    const float* b2e = b2 + e * DIM + n0 + wc * 32;
#pragma unroll
    for (int mt = 0; mt < 4; mt++) {
        const int p0 = m0 + wr * 64 + mt * 16 + gid;
        const int p1 = p0 + 8;
        const bool v0 = p0 < M, v1 = p1 < M;
        int tok0 = 0, slot0 = 0, tok1 = 0, slot1 = 0;
        float w0 = 0.f, w1 = 0.f;
        if (v0) { tok0 = g_ptok[e * PMAX + p0]; slot0 = g_pslot[e * PMAX + p0]; w0 = g_pw[e * PMAX + p0]; }
        if (v1) { tok1 = g_ptok[e * PMAX + p1]; slot1 = g_pslot[e * PMAX + p1]; w1 = g_pw[e * PMAX + p1]; }
        float* d0 = g_pout + ((size_t)(tok0 * 4 + slot0)) * DIM + n0 + wc * 32;
        float* d1 = g_pout + ((size_t)(tok1 * 4 + slot1)) * DIM + n0 + wc * 32;
#pragma unroll
        for (int nt = 0; nt < 4; nt++) {
            const int co = nt * 8 + 2 * tig;
            const float* c = acc[mt][nt];
            if (v0) *(float2*)(d0 + co) = make_float2(w0 * (c[0] + b2e[co]), w0 * (c[1] + b2e[co + 1]));
            if (v1) *(float2*)(d1 + co) = make_float2(w1 * (c[2] + b2e[co]), w1 * (c[3] + b2e[co + 1]));
        }
    }
}

// ---------------- combine ----------------
__global__ void combine_kernel(float* __restrict__ out) {
    const int n = blockIdx.x, tid = threadIdx.x;
    const int ne = g_nent[n];
    const int d = tid * 4;
    float4 s = make_float4(0.f, 0.f, 0.f, 0.f);
    for (int sl = 0; sl < ne; sl++) {
        float4 v = *(const float4*)(g_pout + ((size_t)(n * 4 + sl)) * DIM + d);
        s.x += v.x; s.y += v.y; s.z += v.z; s.w += v.w;
    }
    *(float4*)(out + (size_t)n * DIM + d) = s;
}

// ---------------- launch ----------------
extern "C" void kernel_launch(void* const* d_in, const int* in_sizes, int n_in,
                              void* d_out, int out_size) {
    const float* x  = (const float*)d_in[0];
    const float* rw = (const float*)d_in[1];
    const float* rb = (const float*)d_in[2];
    const float* w1 = (const float*)d_in[3];
    const float* b1 = (const float*)d_in[4];
    const float* w2 = (const float*)d_in[5];
    const float* b2 = (const float*)d_in[6];
    float* out = (float*)d_out;

    cudaFuncSetAttribute(gemm1_tc, cudaFuncAttributeMaxDynamicSharedMemorySize, SMEM_GEMM);
    cudaFuncSetAttribute(gemm2_tc, cudaFuncAttributeMaxDynamicSharedMemorySize, SMEM_GEMM);

    router_split_kernel<<<NTOK / 8, 256>>>(x, rw, rb);
    {
        dim3 tg(DIM / 32, HID / 32, NEXP);
        tsplit_kernel<<<tg, dim3(32, 8)>>>(w1, 0, DIM, HID);
        tsplit_kernel<<<tg, dim3(32, 8)>>>(w2, 1, HID, DIM);
    }
    corr_kernel<<<16, 256>>>();
    zero_cnt_kernel<<<1, 32>>>();
    build_pairs_kernel<<<(NTOK + 255) / 256, 256>>>();

    dim3 gg(HID / 128, PMAX / 128, NEXP);    // (8, 65, 8); dead tiles exit at top
    gemm1_tc<<<gg, 256, SMEM_GEMM>>>(b1);
    gemm2_tc<<<gg, 256, SMEM_GEMM>>>(b2);
    combine_kernel<<<NTOK, 256>>>(out);
}

// round 7
// speedup vs baseline: 2.3611x; 1.0002x over previous
#include <cuda_runtime.h>
#include <cuda_bf16.h>
#include <math.h>
#include <stdint.h>

#define NTOK 8192
#define DIM  1024
#define NEXP 8
#define HID  1024
#define PMAX 8320
#define CAPACITY 1280.0f

#define KC     64            // K elements per pipeline stage
#define NCHUNK 16            // 1024 / 64
#define NSTAGE 3
#define ROWB   144           // 128B data + 16B pad
#define SPLIT_B (128 * ROWB)       // 18432 B: one 128x64 bf16 tile
#define STAGE_B (4 * SPLIT_B)      // Ah, Al, Bh, Bl = 73728
#define HDR     5120               // 512 src pointers (4KB) + 128 pred ints
#define SMEM_GEMM (HDR + NSTAGE * STAGE_B)   // 226304

// ---------------- scratch globals ----------------
__device__ int   g_topi[NTOK * 2];
__device__ float g_topw[NTOK * 2];
__device__ int   g_nent[NTOK];
__device__ int   g_cnt[NEXP];
__device__ int   g_ptok[NEXP * PMAX];
__device__ int   g_pslot[NEXP * PMAX];
__device__ float g_pw[NEXP * PMAX];
__device__ __align__(256) __nv_bfloat16 g_xh[(size_t)NTOK * DIM];
__device__ __align__(256) __nv_bfloat16 g_xl[(size_t)NTOK * DIM];
__device__ __align__(256) __nv_bfloat16 g_w1h[(size_t)NEXP * HID * DIM];   // [e][n][k]
__device__ __align__(256) __nv_bfloat16 g_w1l[(size_t)NEXP * HID * DIM];
__device__ __align__(256) __nv_bfloat16 g_w2h[(size_t)NEXP * DIM * HID];   // [e][n][k]
__device__ __align__(256) __nv_bfloat16 g_w2l[(size_t)NEXP * DIM * HID];
__device__ __align__(256) __nv_bfloat16 g_y1h[(size_t)NEXP * PMAX * HID];
__device__ __align__(256) __nv_bfloat16 g_y1l[(size_t)NEXP * PMAX * HID];
__device__ float g_pout[(size_t)NTOK * 4 * DIM];

// ---------------- small helpers ----------------
__device__ __forceinline__ void split2(float v, __nv_bfloat16& h, __nv_bfloat16& l) {
    h = __float2bfloat16(v);
    l = __float2bfloat16(v - __bfloat162float(h));
}
__device__ __forceinline__ uint32_t packbf2(__nv_bfloat16 a, __nv_bfloat16 b) {
    __nv_bfloat162 t = __halves2bfloat162(a, b);
    return *reinterpret_cast<uint32_t*>(&t);
}
__device__ __forceinline__ float gelu_f(float v) {
    return 0.5f * v * (1.0f + erff(v * 0.70710678118654752f));
}
__device__ __forceinline__ uint32_t smem_u32(const void* p) {
    uint32_t a;
    asm("{ .reg .u64 t; cvta.to.shared.u64 t, %1; cvt.u32.u64 %0, t; }" : "=r"(a) : "l"(p));
    return a;
}

#define LDSM_X4(r, addr) \
    asm volatile("ldmatrix.sync.aligned.m8n8.x4.shared.b16 {%0,%1,%2,%3}, [%4];" \
        : "=r"((r)[0]), "=r"((r)[1]), "=r"((r)[2]), "=r"((r)[3]) : "r"(addr))
#define LDSM_X2(r, addr) \
    asm volatile("ldmatrix.sync.aligned.m8n8.x2.shared.b16 {%0,%1}, [%2];" \
        : "=r"((r)[0]), "=r"((r)[1]) : "r"(addr))
#define MMA16816(c, a, b) \
    asm volatile("mma.sync.aligned.m16n8k16.row.col.f32.bf16.bf16.f32 " \
        "{%0,%1,%2,%3}, {%4,%5,%6,%7}, {%8,%9}, {%0,%1,%2,%3};" \
        : "+f"((c)[0]), "+f"((c)[1]), "+f"((c)[2]), "+f"((c)[3]) \
        : "r"((a)[0]), "r"((a)[1]), "r"((a)[2]), "r"((a)[3]), "r"((b)[0]), "r"((b)[1]))

// ---------------- fused router + x split ----------------
__global__ __launch_bounds__(256) void router_split_kernel(
        const float* __restrict__ x,
        const float* __restrict__ rw,
        const float* __restrict__ rb) {
    __shared__ float s_rw[DIM * 9];          // [k*9 + e]
    const int tid = threadIdx.x, lane = tid & 31, wid = tid >> 5;
    for (int i = tid; i < DIM * NEXP; i += 256) {
        int k = i >> 3, e = i & 7;
        s_rw[k * 9 + e] = rw[i];
    }
    __syncthreads();

    const int n = blockIdx.x * 8 + wid;
    const float* xr = x + (size_t)n * DIM;
    float acc[NEXP];
#pragma unroll
    for (int e = 0; e < NEXP; e++) acc[e] = 0.f;

#pragma unroll 4
    for (int i = 0; i < 16; i++) {
        const int k = i * 64 + lane * 2;
        float2 v = *(const float2*)(xr + k);
        __nv_bfloat16 h0, l0, h1, l1;
        split2(v.x, h0, l0); split2(v.y, h1, l1);
        *(uint32_t*)(g_xh + (size_t)n * DIM + k) = packbf2(h0, h1);
        *(uint32_t*)(g_xl + (size_t)n * DIM + k) = packbf2(l0, l1);
        const float* r0 = s_rw + k * 9;
        const float* r1 = s_rw + (k + 1) * 9;
#pragma unroll
        for (int e = 0; e < NEXP; e++) acc[e] += v.x * r0[e] + v.y * r1[e];
    }
#pragma unroll
    for (int off = 16; off > 0; off >>= 1)
#pragma unroll
        for (int e = 0; e < NEXP; e++)
            acc[e] += __shfl_xor_sync(0xFFFFFFFFu, acc[e], off);

    if (lane == 0) {
        float l[NEXP];
#pragma unroll
        for (int e = 0; e < NEXP; e++) l[e] = acc[e] + rb[e];
        float m = l[0];
#pragma unroll
        for (int e = 1; e < NEXP; e++) m = fmaxf(m, l[e]);
        float p[NEXP], sum = 0.f;
#pragma unroll
        for (int e = 0; e < NEXP; e++) { p[e] = expf(l[e] - m); sum += p[e]; }
#pragma unroll
        for (int e = 0; e < NEXP; e++) p[e] /= sum;
        int i0 = 0;
        for (int e = 1; e < NEXP; e++) if (p[e] > p[i0]) i0 = e;
        int i1 = (i0 == 0) ? 1 : 0;
        for (int e = 0; e < NEXP; e++) if (e != i0 && p[e] > p[i1]) i1 = e;
        float s2 = p[i0] + p[i1];
        g_topi[n * 2 + 0] = i0;  g_topi[n * 2 + 1] = i1;
        g_topw[n * 2 + 0] = p[i0] / s2;  g_topw[n * 2 + 1] = p[i1] / s2;
    }
}

// ---------------- fused corr + dispatch build (ONE block, 1024 threads) ----------------
__global__ __launch_bounds__(1024) void dispatch_kernel() {
    __shared__ float s_wred[32][16];     // per-warp partial corr sums
    __shared__ float s_corr[16];
    __shared__ int   s_cnt[NEXP];
    const int tid = threadIdx.x, lane = tid & 31, wid = tid >> 5;

    // phase 1: corr[r][j] = sum_i top_p[i,j] * (top_i[i,j]==r), deterministic order
    float a[16];
#pragma unroll
    for (int q = 0; q < 16; q++) a[q] = 0.f;
    for (int i = tid; i < NTOK; i += 1024) {
        int e0 = g_topi[i * 2 + 0], e1 = g_topi[i * 2 + 1];
        float w0 = g_topw[i * 2 + 0], w1 = g_topw[i * 2 + 1];
#pragma unroll
        for (int e = 0; e < NEXP; e++) {
            a[e * 2 + 0] += (e0 == e) ? w0 : 0.f;
            a[e * 2 + 1] += (e1 == e) ? w1 : 0.f;
        }
    }
#pragma unroll
    for (int off = 16; off > 0; off >>= 1)
#pragma unroll
        for (int q = 0; q < 16; q++)
            a[q] += __shfl_xor_sync(0xFFFFFFFFu, a[q], off);
    if (lane == 0)
#pragma unroll
        for (int q = 0; q < 16; q++) s_wred[wid][q] = a[q];
    if (tid < NEXP) s_cnt[tid] = 0;
    __syncthreads();
    if (tid < 16) {
        float s = 0.f;
        for (int w = 0; w < 32; w++) s += s_wred[w][tid];   // fixed order
        s_corr[tid] = s;
    }
    __syncthreads();

    // phase 2: build per-expert lists
    for (int n = tid; n < NTOK; n += 1024) {
        int ee[4]; float ww[4]; int ne = 2;
        ee[0] = g_topi[n * 2 + 0]; ww[0] = g_topw[n * 2 + 0];
        ee[1] = g_topi[n * 2 + 1]; ww[1] = g_topw[n * 2 + 1];
        if (n < NEXP) {
#pragma unroll
            for (int j = 0; j < 2; j++) {
                float c = s_corr[n * 2 + j];
                int f = -1;
                for (int s = 0; s < ne; s++) if (ee[s] == j) f = s;
                if (f >= 0) ww[f] += c;
                else if (c != 0.0f) { ee[ne] = j; ww[ne] = c; ne++; }
            }
        }
        g_nent[n] = ne;
        for (int s = 0; s < ne; s++) {
            float w = fminf(ww[s], CAPACITY);
            int e = ee[s];
            int idx = atomicAdd(&s_cnt[e], 1);
            g_ptok[e * PMAX + idx] = n;
            g_pslot[e * PMAX + idx] = s;
            g_pw[e * PMAX + idx] = w;
        }
    }
    __syncthreads();
    if (tid < NEXP) g_cnt[tid] = s_cnt[tid];
}

// ---------------- prep: transpose+split weights  w[e][k][n] -> [e][n][k] hi/lo ----------------
__global__ void tsplit_kernel(const float* __restrict__ w, int which, int R, int C) {
    __shared__ float t[32][33];
    __nv_bfloat16* oh = which ? g_w2h : g_w1h;
    __nv_bfloat16* ol = which ? g_w2l : g_w1l;
    int e = blockIdx.z;
    int k0 = blockIdx.y * 32, n0 = blockIdx.x * 32;
    int tx = threadIdx.x, ty = threadIdx.y;
    const float* wp = w + (size_t)e * R * C;
#pragma unroll
    for (int r = 0; r < 32; r += 8)
        t[ty + r][tx] = wp[(size_t)(k0 + ty + r) * C + n0 + tx];
    __syncthreads();
#pragma unroll
    for (int r = 0; r < 32; r += 8) {
        float v = t[tx][ty + r];
        size_t o = ((size_t)e * C + n0 + ty + r) * R + k0 + tx;
        __nv_bfloat16 h, l; split2(v, h, l);
        oh[o] = h; ol[o] = l;
    }
}

// ---------------- GEMM mainloop (shared by both GEMMs) ----------------
__device__ __forceinline__ void load_stage(char* smem, uint32_t sb, int tid, int c) {
    const __nv_bfloat16* const* s_ptr = (const __nv_bfloat16* const*)smem;   // 512 entries
    const int* s_pred = (const int*)(smem + 4096);                            // 128 entries
    const int kel = c * KC;
    const uint32_t sbase = sb + HDR + (uint32_t)((c % NSTAGE) * STAGE_B);
#pragma unroll
    for (int it = 0; it < 16; it++) {
        const int id = tid + it * 256;
        const int region = id >> 10, within = id & 1023;
        const int row = within >> 3, seg = within & 7;
        const char* src = (const char*)(s_ptr[region * 128 + row] + kel) + seg * 16;
        uint32_t dst = sbase + (uint32_t)(region * SPLIT_B + row * ROWB + seg * 16);
        int sz = (region < 2) ? s_pred[row] : 16;
        asm volatile("cp.async.cg.shared.global [%0], [%1], 16, %2;"
                     :: "r"(dst), "l"(src), "r"(sz) : "memory");
    }
    asm volatile("cp.async.commit_group;" ::: "memory");
}

__device__ __forceinline__ void compute_stage(uint32_t sb, int tid, int buf, float acc[4][4][4]) {
    const int lane = tid & 31, wid = tid >> 5;
    const int wr = wid >> 2, wc = wid & 3;
    const uint32_t base = sb + HDR + (uint32_t)(buf * STAGE_B);
    const int arow = wr * 64 + (lane & 15);
    const int acol = (lane >> 4) * 8;
    const int brow = wc * 32 + (lane & 7);
    const int bcol = ((lane >> 3) & 1) * 8;
#pragma unroll
    for (int kst = 0; kst < 4; kst++) {
        const uint32_t abase = base + (uint32_t)(arow * ROWB + (kst * 16 + acol) * 2);
        const uint32_t bbase = base + (uint32_t)(2 * SPLIT_B + brow * ROWB + (kst * 16 + bcol) * 2);
        uint32_t ah[4][4], al[4][4], bh[4][2], bl[4][2];
#pragma unroll
        for (int mt = 0; mt < 4; mt++) {
            LDSM_X4(ah[mt], abase + mt * 16 * ROWB);
            LDSM_X4(al[mt], abase + SPLIT_B + mt * 16 * ROWB);
        }
#pragma unroll
        for (int nt = 0; nt < 4; nt++) {
            LDSM_X2(bh[nt], bbase + nt * 8 * ROWB);
            LDSM_X2(bl[nt], bbase + SPLIT_B + nt * 8 * ROWB);
        }
#pragma unroll
        for (int mt = 0; mt < 4; mt++)
#pragma unroll
            for (int nt = 0; nt < 4; nt++) {
                MMA16816(acc[mt][nt], ah[mt], bh[nt]);
                MMA16816(acc[mt][nt], ah[mt], bl[nt]);
                MMA16816(acc[mt][nt], al[mt], bh[nt]);
            }
    }
}

__device__ __forceinline__ void gemm_mainloop(char* smem, uint32_t sb, int tid, float acc[4][4][4]) {
#pragma unroll
    for (int mt = 0; mt < 4; mt++)
#pragma unroll
        for (int nt = 0; nt < 4; nt++)
#pragma unroll
            for (int i = 0; i < 4; i++) acc[mt][nt][i] = 0.f;
    load_stage(smem, sb, tid, 0);
    load_stage(smem, sb, tid, 1);
    load_stage(smem, sb, tid, 2);
#pragma unroll 1
    for (int c = 0; c < NCHUNK; c++) {
        if (c <= NCHUNK - 3)      asm volatile("cp.async.wait_group 2;" ::: "memory");
        else if (c == NCHUNK - 2) asm volatile("cp.async.wait_group 1;" ::: "memory");
        else                      asm volatile("cp.async.wait_group 0;" ::: "memory");
        __syncthreads();
        compute_stage(sb, tid, c % NSTAGE, acc);
        __syncthreads();
        if (c + 3 < NCHUNK) load_stage(smem, sb, tid, c + 3);
    }
}

// ---------------- GEMM1: y1 = gelu(w * (x @ W1) + b1) -> bf16 hi/lo ----------------
__global__ __launch_bounds__(256, 1) void gemm1_tc(const float* __restrict__ b1) {
    const int e = blockIdx.z;
    const int M = g_cnt[e];
    const int m0 = blockIdx.y * 128;
    if (m0 >= M) return;
    const int n0 = blockIdx.x * 128;
    extern __shared__ char smem[];
    const uint32_t sb = smem_u32(smem);
    const int tid = threadIdx.x;

    {
        const __nv_bfloat16** s_ptr = (const __nv_bfloat16**)smem;
        int* s_pred = (int*)(smem + 4096);
        if (tid < 128) {
            int p = m0 + tid;
            bool v = p < M;
            int tok = v ? g_ptok[e * PMAX + p] : 0;
            s_ptr[0 * 128 + tid] = g_xh + (size_t)tok * DIM;
            s_ptr[1 * 128 + tid] = g_xl + (size_t)tok * DIM;
            s_ptr[2 * 128 + tid] = g_w1h + ((size_t)e * HID + n0 + tid) * DIM;
            s_ptr[3 * 128 + tid] = g_w1l + ((size_t)e * HID + n0 + tid) * DIM;
            s_pred[tid] = v ? 16 : 0;
        }
    }
    __syncthreads();

    float acc[4][4][4];
    gemm_mainloop(smem, sb, tid, acc);

    const int lane = tid & 31, wid = tid >> 5;
    const int wr = wid >> 2, wc = wid & 3;
    const int gid = lane >> 2, tig = lane & 3;
    const float* b1e = b1 + e * HID + n0 + wc * 32;
#pragma unroll
    for (int mt = 0; mt < 4; mt++) {
        const int p0 = m0 + wr * 64 + mt * 16 + gid;
        const int p1 = p0 + 8;
        const bool v0 = p0 < M, v1 = p1 < M;
        const float w0 = v0 ? g_pw[e * PMAX + p0] : 0.f;
        const float w1 = v1 ? g_pw[e * PMAX + p1] : 0.f;
        __nv_bfloat16* oh0 = g_y1h + ((size_t)(e * PMAX + p0)) * HID + n0 + wc * 32;
        __nv_bfloat16* ol0 = g_y1l + ((size_t)(e * PMAX + p0)) * HID + n0 + wc * 32;
        __nv_bfloat16* oh1 = g_y1h + ((size_t)(e * PMAX + p1)) * HID + n0 + wc * 32;
        __nv_bfloat16* ol1 = g_y1l + ((size_t)(e * PMAX + p1)) * HID + n0 + wc * 32;
#pragma unroll
        for (int nt = 0; nt < 4; nt++) {
            const int co = nt * 8 + 2 * tig;
            const float* c = acc[mt][nt];
            if (v0) {
                float t0 = gelu_f(w0 * c[0] + b1e[co]);
                float t1 = gelu_f(w0 * c[1] + b1e[co + 1]);
                __nv_bfloat16 h0, l0, h1, l1;
                split2(t0, h0, l0); split2(t1, h1, l1);
                *(uint32_t*)(oh0 + co) = packbf2(h0, h1);
                *(uint32_t*)(ol0 + co) = packbf2(l0, l1);
            }
            if (v1) {
                float t0 = gelu_f(w1 * c[2] + b1e[co]);
                float t1 = gelu_f(w1 * c[3] + b1e[co + 1]);
                __nv_bfloat16 h0, l0, h1, l1;
                split2(t0, h0, l0); split2(t1, h1, l1);
                *(uint32_t*)(oh1 + co) = packbf2(h0, h1);
                *(uint32_t*)(ol1 + co) = packbf2(l0, l1);
            }
        }
    }
}

// ---------------- GEMM2: pout = w * (y1 @ W2 + b2) ----------------
__global__ __launch_bounds__(256, 1) void gemm2_tc(const float* __restrict__ b2) {
    const int e = blockIdx.z;
    const int M = g_cnt[e];
    const int m0 = blockIdx.y * 128;
    if (m0 >= M) return;
    const int n0 = blockIdx.x * 128;
    extern __shared__ char smem[];
    const uint32_t sb = smem_u32(smem);
    const int tid = threadIdx.x;

    {
        const __nv_bfloat16** s_ptr = (const __nv_bfloat16**)smem;
        int* s_pred = (int*)(smem + 4096);
        if (tid < 128) {
            int p = m0 + tid;
            bool v = p < M;
            size_t ar = ((size_t)(e * PMAX + (v ? p : 0))) * HID;
            s_ptr[0 * 128 + tid] = g_y1h + ar;
            s_ptr[1 * 128 + tid] = g_y1l + ar;
            s_ptr[2 * 128 + tid] = g_w2h + ((size_t)e * DIM + n0 + tid) * HID;
            s_ptr[3 * 128 + tid] = g_w2l + ((size_t)e * DIM + n0 + tid) * HID;
            s_pred[tid] = v ? 16 : 0;
        }
    }
    __syncthreads();

    float acc[4][4][4];
    gemm_mainloop(smem, sb, tid, acc);

    const int lane = tid & 31, wid = tid >> 5;
    const int wr = wid >> 2, wc = wid & 3;
    const int gid = lane >> 2, tig = lane & 3;
    const float* b2e = b2 + e * DIM + n0 + wc * 32;
#pragma unroll
    for (int mt = 0; mt < 4; mt++) {
        const int p0 = m0 + wr * 64 + mt * 16 + gid;
        const int p1 = p0 + 8;
        const bool v0 = p0 < M, v1 = p1 < M;
        int tok0 = 0, slot0 = 0, tok1 = 0, slot1 = 0;
        float w0 = 0.f, w1 = 0.f;
        if (v0) { tok0 = g_ptok[e * PMAX + p0]; slot0 = g_pslot[e * PMAX + p0]; w0 = g_pw[e * PMAX + p0]; }
        if (v1) { tok1 = g_ptok[e * PMAX + p1]; slot1 = g_pslot[e * PMAX + p1]; w1 = g_pw[e * PMAX + p1]; }
        float* d0 = g_pout + ((size_t)(tok0 * 4 + slot0)) * DIM + n0 + wc * 32;
        float* d1 = g_pout + ((size_t)(tok1 * 4 + slot1)) * DIM + n0 + wc * 32;
#pragma unroll
        for (int nt = 0; nt < 4; nt++) {
            const int co = nt * 8 + 2 * tig;
            const float* c = acc[mt][nt];
            if (v0) *(float2*)(d0 + co) = make_float2(w0 * (c[0] + b2e[co]), w0 * (c[1] + b2e[co + 1]));
            if (v1) *(float2*)(d1 + co) = make_float2(w1 * (c[2] + b2e[co]), w1 * (c[3] + b2e[co + 1]));
        }
    }
}

// ---------------- combine ----------------
__global__ void combine_kernel(float* __restrict__ out) {
    const int n = blockIdx.x, tid = threadIdx.x;
    const int ne = g_nent[n];
    const int d = tid * 4;
    float4 s = make_float4(0.f, 0.f, 0.f, 0.f);
    for (int sl = 0; sl < ne; sl++) {
        float4 v = *(const float4*)(g_pout + ((size_t)(n * 4 + sl)) * DIM + d);
        s.x += v.x; s.y += v.y; s.z += v.z; s.w += v.w;
    }
    *(float4*)(out + (size_t)n * DIM + d) = s;
}

// ---------------- launch ----------------
extern "C" void kernel_launch(void* const* d_in, const int* in_sizes, int n_in,
                              void* d_out, int out_size) {
    const float* x  = (const float*)d_in[0];
    const float* rw = (const float*)d_in[1];
    const float* rb = (const float*)d_in[2];
    const float* w1 = (const float*)d_in[3];
    const float* b1 = (const float*)d_in[4];
    const float* w2 = (const float*)d_in[5];
    const float* b2 = (const float*)d_in[6];
    float* out = (float*)d_out;

    cudaFuncSetAttribute(gemm1_tc, cudaFuncAttributeMaxDynamicSharedMemorySize, SMEM_GEMM);
    cudaFuncSetAttribute(gemm2_tc, cudaFuncAttributeMaxDynamicSharedMemorySize, SMEM_GEMM);

    dim3 gg(HID / 128, PMAX / 128, NEXP);    // (8, 65, 8); dead tiles exit at top
    dim3 tg(DIM / 32, HID / 32, NEXP);

    // order chosen so gemm1_tc is launch index 3 (the one ncu captures)
    router_split_kernel<<<NTOK / 8, 256>>>(x, rw, rb);        // 0
    dispatch_kernel<<<1, 1024>>>();                            // 1
    tsplit_kernel<<<tg, dim3(32, 8)>>>(w1, 0, DIM, HID);       // 2
    gemm1_tc<<<gg, 256, SMEM_GEMM>>>(b1);                      // 3  <- profiled
    tsplit_kernel<<<tg, dim3(32, 8)>>>(w2, 1, HID, DIM);       // 4
    gemm2_tc<<<gg, 256, SMEM_GEMM>>>(b2);                      // 5
    combine_kernel<<<NTOK, 256>>>(out);                        // 6
}

// round 8
// speedup vs baseline: 2.4951x; 1.0568x over previous
#include <cuda_runtime.h>
#include <cuda_bf16.h>
#include <math.h>
#include <stdint.h>

#define NTOK 8192
#define DIM  1024
#define NEXP 8
#define HID  1024
#define PMAX 8320
#define CAPACITY 1280.0f

#define KC     32            // K elements per pipeline stage
#define NCHUNK 32            // 1024 / 32
#define NSTAGE 2
#define ROWB   80            // 64B data + 16B pad (16B-aligned rows for ldmatrix)
#define SPLIT_B (128 * ROWB)       // 10240 B: one 128x32 bf16 tile
#define STAGE_B (4 * SPLIT_B)      // Ah, Al, Bh, Bl = 40960
#define HDR     5120               // 512 src pointers (4KB) + 128 pred ints
#define SMEM_GEMM (HDR + NSTAGE * STAGE_B)   // 87040 -> 2 CTAs/SM

// ---------------- scratch globals ----------------
__device__ int   g_topi[NTOK * 2];
__device__ float g_topw[NTOK * 2];
__device__ int   g_nent[NTOK];
__device__ int   g_cnt[NEXP];
__device__ int   g_ptok[NEXP * PMAX];
__device__ int   g_pslot[NEXP * PMAX];
__device__ float g_pw[NEXP * PMAX];
__device__ __align__(256) __nv_bfloat16 g_xh[(size_t)NTOK * DIM];
__device__ __align__(256) __nv_bfloat16 g_xl[(size_t)NTOK * DIM];
__device__ __align__(256) __nv_bfloat16 g_w1h[(size_t)NEXP * HID * DIM];   // [e][n][k]
__device__ __align__(256) __nv_bfloat16 g_w1l[(size_t)NEXP * HID * DIM];
__device__ __align__(256) __nv_bfloat16 g_w2h[(size_t)NEXP * DIM * HID];   // [e][n][k]
__device__ __align__(256) __nv_bfloat16 g_w2l[(size_t)NEXP * DIM * HID];
__device__ __align__(256) __nv_bfloat16 g_y1h[(size_t)NEXP * PMAX * HID];
__device__ __align__(256) __nv_bfloat16 g_y1l[(size_t)NEXP * PMAX * HID];
__device__ float g_pout[(size_t)NTOK * 4 * DIM];

// ---------------- small helpers ----------------
__device__ __forceinline__ void split2(float v, __nv_bfloat16& h, __nv_bfloat16& l) {
    h = __float2bfloat16(v);
    l = __float2bfloat16(v - __bfloat162float(h));
}
__device__ __forceinline__ uint32_t packbf2(__nv_bfloat16 a, __nv_bfloat16 b) {
    __nv_bfloat162 t = __halves2bfloat162(a, b);
    return *reinterpret_cast<uint32_t*>(&t);
}
__device__ __forceinline__ float gelu_f(float v) {
    return 0.5f * v * (1.0f + erff(v * 0.70710678118654752f));
}
__device__ __forceinline__ uint32_t smem_u32(const void* p) {
    uint32_t a;
    asm("{ .reg .u64 t; cvta.to.shared.u64 t, %1; cvt.u32.u64 %0, t; }" : "=r"(a) : "l"(p));
    return a;
}

#define LDSM_X4(r, addr) \
    asm volatile("ldmatrix.sync.aligned.m8n8.x4.shared.b16 {%0,%1,%2,%3}, [%4];" \
        : "=r"((r)[0]), "=r"((r)[1]), "=r"((r)[2]), "=r"((r)[3]) : "r"(addr))
#define LDSM_X2(r, addr) \
    asm volatile("ldmatrix.sync.aligned.m8n8.x2.shared.b16 {%0,%1}, [%2];" \
        : "=r"((r)[0]), "=r"((r)[1]) : "r"(addr))
#define MMA16816(c, a, b) \
    asm volatile("mma.sync.aligned.m16n8k16.row.col.f32.bf16.bf16.f32 " \
        "{%0,%1,%2,%3}, {%4,%5,%6,%7}, {%8,%9}, {%0,%1,%2,%3};" \
        : "+f"((c)[0]), "+f"((c)[1]), "+f"((c)[2]), "+f"((c)[3]) \
        : "r"((a)[0]), "r"((a)[1]), "r"((a)[2]), "r"((a)[3]), "r"((b)[0]), "r"((b)[1]))

// ---------------- fused router + x split ----------------
__global__ __launch_bounds__(256) void router_split_kernel(
        const float* __restrict__ x,
        const float* __restrict__ rw,
        const float* __restrict__ rb) {
    __shared__ float s_rw[DIM * 9];          // [k*9 + e]
    const int tid = threadIdx.x, lane = tid & 31, wid = tid >> 5;
    for (int i = tid; i < DIM * NEXP; i += 256) {
        int k = i >> 3, e = i & 7;
        s_rw[k * 9 + e] = rw[i];
    }
    __syncthreads();

    const int n = blockIdx.x * 8 + wid;
    const float* xr = x + (size_t)n * DIM;
    float acc[NEXP];
#pragma unroll
    for (int e = 0; e < NEXP; e++) acc[e] = 0.f;

#pragma unroll 4
    for (int i = 0; i < 16; i++) {
        const int k = i * 64 + lane * 2;
        float2 v = *(const float2*)(xr + k);
        __nv_bfloat16 h0, l0, h1, l1;
        split2(v.x, h0, l0); split2(v.y, h1, l1);
        *(uint32_t*)(g_xh + (size_t)n * DIM + k) = packbf2(h0, h1);
        *(uint32_t*)(g_xl + (size_t)n * DIM + k) = packbf2(l0, l1);
        const float* r0 = s_rw + k * 9;
        const float* r1 = s_rw + (k + 1) * 9;
#pragma unroll
        for (int e = 0; e < NEXP; e++) acc[e] += v.x * r0[e] + v.y * r1[e];
    }
#pragma unroll
    for (int off = 16; off > 0; off >>= 1)
#pragma unroll
        for (int e = 0; e < NEXP; e++)
            acc[e] += __shfl_xor_sync(0xFFFFFFFFu, acc[e], off);

    if (lane == 0) {
        float l[NEXP];
#pragma unroll
        for (int e = 0; e < NEXP; e++) l[e] = acc[e] + rb[e];
        float m = l[0];
#pragma unroll
        for (int e = 1; e < NEXP; e++) m = fmaxf(m, l[e]);
        float p[NEXP], sum = 0.f;
#pragma unroll
        for (int e = 0; e < NEXP; e++) { p[e] = expf(l[e] - m); sum += p[e]; }
#pragma unroll
        for (int e = 0; e < NEXP; e++) p[e] /= sum;
        int i0 = 0;
        for (int e = 1; e < NEXP; e++) if (p[e] > p[i0]) i0 = e;
        int i1 = (i0 == 0) ? 1 : 0;
        for (int e = 0; e < NEXP; e++) if (e != i0 && p[e] > p[i1]) i1 = e;
        float s2 = p[i0] + p[i1];
        g_topi[n * 2 + 0] = i0;  g_topi[n * 2 + 1] = i1;
        g_topw[n * 2 + 0] = p[i0] / s2;  g_topw[n * 2 + 1] = p[i1] / s2;
    }
}

// ---------------- fused corr + dispatch build (ONE block, 1024 threads) ----------------
__global__ __launch_bounds__(1024) void dispatch_kernel() {
    __shared__ float s_wred[32][16];
    __shared__ float s_corr[16];
    __shared__ int   s_cnt[NEXP];
    const int tid = threadIdx.x, lane = tid & 31, wid = tid >> 5;

    float a[16];
#pragma unroll
    for (int q = 0; q < 16; q++) a[q] = 0.f;
    for (int i = tid; i < NTOK; i += 1024) {
        int e0 = g_topi[i * 2 + 0], e1 = g_topi[i * 2 + 1];
        float w0 = g_topw[i * 2 + 0], w1 = g_topw[i * 2 + 1];
#pragma unroll
        for (int e = 0; e < NEXP; e++) {
            a[e * 2 + 0] += (e0 == e) ? w0 : 0.f;
            a[e * 2 + 1] += (e1 == e) ? w1 : 0.f;
        }
    }
#pragma unroll
    for (int off = 16; off > 0; off >>= 1)
#pragma unroll
        for (int q = 0; q < 16; q++)
            a[q] += __shfl_xor_sync(0xFFFFFFFFu, a[q], off);
    if (lane == 0)
#pragma unroll
        for (int q = 0; q < 16; q++) s_wred[wid][q] = a[q];
    if (tid < NEXP) s_cnt[tid] = 0;
    __syncthreads();
    if (tid < 16) {
        float s = 0.f;
        for (int w = 0; w < 32; w++) s += s_wred[w][tid];
        s_corr[tid] = s;
    }
    __syncthreads();

    for (int n = tid; n < NTOK; n += 1024) {
        int ee[4]; float ww[4]; int ne = 2;
        ee[0] = g_topi[n * 2 + 0]; ww[0] = g_topw[n * 2 + 0];
        ee[1] = g_topi[n * 2 + 1]; ww[1] = g_topw[n * 2 + 1];
        if (n < NEXP) {
#pragma unroll
            for (int j = 0; j < 2; j++) {
                float c = s_corr[n * 2 + j];
                int f = -1;
                for (int s = 0; s < ne; s++) if (ee[s] == j) f = s;
                if (f >= 0) ww[f] += c;
                else if (c != 0.0f) { ee[ne] = j; ww[ne] = c; ne++; }
            }
        }
        g_nent[n] = ne;
        for (int s = 0; s < ne; s++) {
            float w = fminf(ww[s], CAPACITY);
            int e = ee[s];
            int idx = atomicAdd(&s_cnt[e], 1);
            g_ptok[e * PMAX + idx] = n;
            g_pslot[e * PMAX + idx] = s;
            g_pw[e * PMAX + idx] = w;
        }
    }
    __syncthreads();
    if (tid < NEXP) g_cnt[tid] = s_cnt[tid];
}

// ---------------- prep: transpose+split weights  w[e][k][n] -> [e][n][k] hi/lo ----------------
__global__ void tsplit_kernel(const float* __restrict__ w, int which, int R, int C) {
    __shared__ float t[32][33];
    __nv_bfloat16* oh = which ? g_w2h : g_w1h;
    __nv_bfloat16* ol = which ? g_w2l : g_w1l;
    int e = blockIdx.z;
    int k0 = blockIdx.y * 32, n0 = blockIdx.x * 32;
    int tx = threadIdx.x, ty = threadIdx.y;
    const float* wp = w + (size_t)e * R * C;
#pragma unroll
    for (int r = 0; r < 32; r += 8)
        t[ty + r][tx] = wp[(size_t)(k0 + ty + r) * C + n0 + tx];
    __syncthreads();
#pragma unroll
    for (int r = 0; r < 32; r += 8) {
        float v = t[tx][ty + r];
        size_t o = ((size_t)e * C + n0 + ty + r) * R + k0 + tx;
        __nv_bfloat16 h, l; split2(v, h, l);
        oh[o] = h; ol[o] = l;
    }
}

// ---------------- GEMM mainloop (shared by both GEMMs) ----------------
__device__ __forceinline__ void load_stage(char* smem, uint32_t sb, int tid, int c) {
    const __nv_bfloat16* const* s_ptr = (const __nv_bfloat16* const*)smem;   // 512 entries
    const int* s_pred = (const int*)(smem + 4096);                            // 128 entries
    const int kel = c * KC;
    const uint32_t sbase = sb + HDR + (uint32_t)((c & 1) * STAGE_B);
#pragma unroll
    for (int it = 0; it < 8; it++) {
        const int id = tid + it * 256;
        const int region = id >> 9, within = id & 511;
        const int row = within >> 2, seg = within & 3;
        const char* src = (const char*)(s_ptr[region * 128 + row] + kel) + seg * 16;
        uint32_t dst = sbase + (uint32_t)(region * SPLIT_B + row * ROWB + seg * 16);
        int sz = (region < 2) ? s_pred[row] : 16;
        asm volatile("cp.async.cg.shared.global [%0], [%1], 16, %2;"
                     :: "r"(dst), "l"(src), "r"(sz) : "memory");
    }
    asm volatile("cp.async.commit_group;" ::: "memory");
}

__device__ __forceinline__ void compute_stage(uint32_t sb, int tid, int buf, float acc[4][4][4]) {
    const int lane = tid & 31, wid = tid >> 5;
    const int wr = wid >> 2, wc = wid & 3;
    const uint32_t base = sb + HDR + (uint32_t)(buf * STAGE_B);
    const int arow = wr * 64 + (lane & 15);
    const int acol = (lane >> 4) * 8;
    const int brow = wc * 32 + (lane & 7);
    const int bcol = ((lane >> 3) & 1) * 8;
#pragma unroll
    for (int kst = 0; kst < 2; kst++) {
        const uint32_t abase = base + (uint32_t)(arow * ROWB + (kst * 16 + acol) * 2);
        const uint32_t bbase = base + (uint32_t)(2 * SPLIT_B + brow * ROWB + (kst * 16 + bcol) * 2);
        uint32_t ah[4][4], al[4][4], bh[4][2], bl[4][2];
#pragma unroll
        for (int mt = 0; mt < 4; mt++) {
            LDSM_X4(ah[mt], abase + mt * 16 * ROWB);
            LDSM_X4(al[mt], abase + SPLIT_B + mt * 16 * ROWB);
        }
#pragma unroll
        for (int nt = 0; nt < 4; nt++) {
            LDSM_X2(bh[nt], bbase + nt * 8 * ROWB);
            LDSM_X2(bl[nt], bbase + SPLIT_B + nt * 8 * ROWB);
        }
#pragma unroll
        for (int mt = 0; mt < 4; mt++)
#pragma unroll
            for (int nt = 0; nt < 4; nt++) {
                MMA16816(acc[mt][nt], ah[mt], bh[nt]);
                MMA16816(acc[mt][nt], ah[mt], bl[nt]);
                MMA16816(acc[mt][nt], al[mt], bh[nt]);
            }
    }
}

__device__ __forceinline__ void gemm_mainloop(char* smem, uint32_t sb, int tid, float acc[4][4][4]) {
#pragma unroll
    for (int mt = 0; mt < 4; mt++)
#pragma unroll
        for (int nt = 0; nt < 4; nt++)
#pragma unroll
            for (int i = 0; i < 4; i++) acc[mt][nt][i] = 0.f;
    load_stage(smem, sb, tid, 0);
#pragma unroll 1
    for (int c = 0; c < NCHUNK; c++) {
        if (c + 1 < NCHUNK) {
            load_stage(smem, sb, tid, c + 1);
            asm volatile("cp.async.wait_group 1;" ::: "memory");
        } else {
            asm volatile("cp.async.wait_group 0;" ::: "memory");
        }
        __syncthreads();
        compute_stage(sb, tid, c & 1, acc);
        __syncthreads();
    }
}

// ---------------- GEMM1: y1 = gelu(w * (x @ W1) + b1) -> bf16 hi/lo ----------------
__global__ __launch_bounds__(256, 2) void gemm1_tc(const float* __restrict__ b1) {
    const int e = blockIdx.z;
    const int M = g_cnt[e];
    const int m0 = blockIdx.y * 128;
    if (m0 >= M) return;
    const int n0 = blockIdx.x * 128;
    extern __shared__ char smem[];
    const uint32_t sb = smem_u32(smem);
    const int tid = threadIdx.x;

    {
        const __nv_bfloat16** s_ptr = (const __nv_bfloat16**)smem;
        int* s_pred = (int*)(smem + 4096);
        if (tid < 128) {
            int p = m0 + tid;
            bool v = p < M;
            int tok = v ? g_ptok[e * PMAX + p] : 0;
            s_ptr[0 * 128 + tid] = g_xh + (size_t)tok * DIM;
            s_ptr[1 * 128 + tid] = g_xl + (size_t)tok * DIM;
            s_ptr[2 * 128 + tid] = g_w1h + ((size_t)e * HID + n0 + tid) * DIM;
            s_ptr[3 * 128 + tid] = g_w1l + ((size_t)e * HID + n0 + tid) * DIM;
            s_pred[tid] = v ? 16 : 0;
        }
    }
    __syncthreads();

    float acc[4][4][4];
    gemm_mainloop(smem, sb, tid, acc);

    const int lane = tid & 31, wid = tid >> 5;
    const int wr = wid >> 2, wc = wid & 3;
    const int gid = lane >> 2, tig = lane & 3;
    const float* b1e = b1 + e * HID + n0 + wc * 32;
#pragma unroll
    for (int mt = 0; mt < 4; mt++) {
        const int p0 = m0 + wr * 64 + mt * 16 + gid;
        const int p1 = p0 + 8;
        const bool v0 = p0 < M, v1 = p1 < M;
        const float w0 = v0 ? g_pw[e * PMAX + p0] : 0.f;
        const float w1 = v1 ? g_pw[e * PMAX + p1] : 0.f;
        __nv_bfloat16* oh0 = g_y1h + ((size_t)(e * PMAX + p0)) * HID + n0 + wc * 32;
        __nv_bfloat16* ol0 = g_y1l + ((size_t)(e * PMAX + p0)) * HID + n0 + wc * 32;
        __nv_bfloat16* oh1 = g_y1h + ((size_t)(e * PMAX + p1)) * HID + n0 + wc * 32;
        __nv_bfloat16* ol1 = g_y1l + ((size_t)(e * PMAX + p1)) * HID + n0 + wc * 32;
#pragma unroll
        for (int nt = 0; nt < 4; nt++) {
            const int co = nt * 8 + 2 * tig;
            const float* c = acc[mt][nt];
            if (v0) {
                float t0 = gelu_f(w0 * c[0] + b1e[co]);
                float t1 = gelu_f(w0 * c[1] + b1e[co + 1]);
                __nv_bfloat16 h0, l0, h1, l1;
                split2(t0, h0, l0); split2(t1, h1, l1);
                *(uint32_t*)(oh0 + co) = packbf2(h0, h1);
                *(uint32_t*)(ol0 + co) = packbf2(l0, l1);
            }
            if (v1) {
                float t0 = gelu_f(w1 * c[2] + b1e[co]);
                float t1 = gelu_f(w1 * c[3] + b1e[co + 1]);
                __nv_bfloat16 h0, l0, h1, l1;
                split2(t0, h0, l0); split2(t1, h1, l1);
                *(uint32_t*)(oh1 + co) = packbf2(h0, h1);
                *(uint32_t*)(ol1 + co) = packbf2(l0, l1);
            }
        }
    }
}

// ---------------- GEMM2: pout = w * (y1 @ W2 + b2) ----------------
__global__ __launch_bounds__(256, 2) void gemm2_tc(const float* __restrict__ b2) {
    const int e = blockIdx.z;
    const int M = g_cnt[e];
    const int m0 = blockIdx.y * 128;
    if (m0 >= M) return;
    const int n0 = blockIdx.x * 128;
    extern __shared__ char smem[];
    const uint32_t sb = smem_u32(smem);
    const int tid = threadIdx.x;

    {
        const __nv_bfloat16** s_ptr = (const __nv_bfloat16**)smem;
        int* s_pred = (int*)(smem + 4096);
        if (tid < 128) {
            int p = m0 + tid;
            bool v = p < M;
            size_t ar = ((size_t)(e * PMAX + (v ? p : 0))) * HID;
            s_ptr[0 * 128 + tid] = g_y1h + ar;
            s_ptr[1 * 128 + tid] = g_y1l + ar;
            s_ptr[2 * 128 + tid] = g_w2h + ((size_t)e * DIM + n0 + tid) * HID;
            s_ptr[3 * 128 + tid] = g_w2l + ((size_t)e * DIM + n0 + tid) * HID;
            s_pred[tid] = v ? 16 : 0;
        }
    }
    __syncthreads();

    float acc[4][4][4];
    gemm_mainloop(smem, sb, tid, acc);

    const int lane = tid & 31, wid = tid >> 5;
    const int wr = wid >> 2, wc = wid & 3;
    const int gid = lane >> 2, tig = lane & 3;
    const float* b2e = b2 + e * DIM + n0 + wc * 32;
#pragma unroll
    for (int mt = 0; mt < 4; mt++) {
        const int p0 = m0 + wr * 64 + mt * 16 + gid;
        const int p1 = p0 + 8;
        const bool v0 = p0 < M, v1 = p1 < M;
        int tok0 = 0, slot0 = 0, tok1 = 0, slot1 = 0;
        float w0 = 0.f, w1 = 0.f;
        if (v0) { tok0 = g_ptok[e * PMAX + p0]; slot0 = g_pslot[e * PMAX + p0]; w0 = g_pw[e * PMAX + p0]; }
        if (v1) { tok1 = g_ptok[e * PMAX + p1]; slot1 = g_pslot[e * PMAX + p1]; w1 = g_pw[e * PMAX + p1]; }
        float* d0 = g_pout + ((size_t)(tok0 * 4 + slot0)) * DIM + n0 + wc * 32;
        float* d1 = g_pout + ((size_t)(tok1 * 4 + slot1)) * DIM + n0 + wc * 32;
#pragma unroll
        for (int nt = 0; nt < 4; nt++) {
            const int co = nt * 8 + 2 * tig;
            const float* c = acc[mt][nt];
            if (v0) *(float2*)(d0 + co) = make_float2(w0 * (c[0] + b2e[co]), w0 * (c[1] + b2e[co + 1]));
            if (v1) *(float2*)(d1 + co) = make_float2(w1 * (c[2] + b2e[co]), w1 * (c[3] + b2e[co + 1]));
        }
    }
}

// ---------------- combine ----------------
__global__ void combine_kernel(float* __restrict__ out) {
    const int n = blockIdx.x, tid = threadIdx.x;
    const int ne = g_nent[n];
    const int d = tid * 4;
    float4 s = make_float4(0.f, 0.f, 0.f, 0.f);
    for (int sl = 0; sl < ne; sl++) {
        float4 v = *(const float4*)(g_pout + ((size_t)(n * 4 + sl)) * DIM + d);
        s.x += v.x; s.y += v.y; s.z += v.z; s.w += v.w;
    }
    *(float4*)(out + (size_t)n * DIM + d) = s;
}

// ---------------- launch ----------------
extern "C" void kernel_launch(void* const* d_in, const int* in_sizes, int n_in,
                              void* d_out, int out_size) {
    const float* x  = (const float*)d_in[0];
    const float* rw = (const float*)d_in[1];
    const float* rb = (const float*)d_in[2];
    const float* w1 = (const float*)d_in[3];
    const float* b1 = (const float*)d_in[4];
    const float* w2 = (const float*)d_in[5];
    const float* b2 = (const float*)d_in[6];
    float* out = (float*)d_out;

    cudaFuncSetAttribute(gemm1_tc, cudaFuncAttributeMaxDynamicSharedMemorySize, SMEM_GEMM);
    cudaFuncSetAttribute(gemm2_tc, cudaFuncAttributeMaxDynamicSharedMemorySize, SMEM_GEMM);

    dim3 gg(HID / 128, PMAX / 128, NEXP);    // (8, 65, 8); dead tiles exit at top
    dim3 tg(DIM / 32, HID / 32, NEXP);

    // order chosen so gemm1_tc is launch index 3 (the one ncu captures)
    router_split_kernel<<<NTOK / 8, 256>>>(x, rw, rb);        // 0
    dispatch_kernel<<<1, 1024>>>();                            // 1
    tsplit_kernel<<<tg, dim3(32, 8)>>>(w1, 0, DIM, HID);       // 2
    gemm1_tc<<<gg, 256, SMEM_GEMM>>>(b1);                      // 3  <- profiled
    tsplit_kernel<<<tg, dim3(32, 8)>>>(w2, 1, HID, DIM);       // 4
    gemm2_tc<<<gg, 256, SMEM_GEMM>>>(b2);                      // 5
    combine_kernel<<<NTOK, 256>>>(out);                        // 6
}

// round 10
// speedup vs baseline: 3.8755x; 1.5532x over previous
#include <cuda_runtime.h>
#include <cuda_fp16.h>
#include <math.h>
#include <stdint.h>

#define NTOK 8192
#define DIM  1024
#define NEXP 8
#define HID  1024
#define PMAX 8320
#define CAPACITY 1280.0f

#define KC     64            // K elements per pipeline stage (fp16: 128B rows)
#define NCHUNK 16            // 1024 / 64
#define ROWB   128           // fp16 row bytes, swizzled (no pad)
#define SPLIT_B (128 * ROWB)       // 16384 B: one 128x64 fp16 tile
#define STAGE_B (3 * SPLIT_B)      // Ah, Al, B = 49152
#define HDR     4096               // 384 src ptrs (3KB) + 128 pred ints (512B)
#define SMEM_GEMM (HDR + 2 * STAGE_B)   // 102400 -> 2 CTAs/SM

// ---------------- scratch globals ----------------
__device__ int   g_topi[NTOK * 2];
__device__ float g_topw[NTOK * 2];
__device__ int   g_nent[NTOK];
__device__ int   g_cnt[NEXP];
__device__ int   g_ptok[NEXP * PMAX];
__device__ int   g_pslot[NEXP * PMAX];
__device__ float g_pw[NEXP * PMAX];
__device__ __align__(256) __half g_xh[(size_t)NTOK * DIM];
__device__ __align__(256) __half g_xl[(size_t)NTOK * DIM];
__device__ __align__(256) __half g_w1[(size_t)NEXP * HID * DIM];   // [e][n][k] fp16
__device__ __align__(256) __half g_w2[(size_t)NEXP * DIM * HID];   // [e][n][k] fp16
__device__ __align__(256) __half g_y1h[(size_t)NEXP * PMAX * HID];
__device__ __align__(256) __half g_y1l[(size_t)NEXP * PMAX * HID];
__device__ float g_pout[(size_t)NTOK * 4 * DIM];

// ---------------- small helpers ----------------
__device__ __forceinline__ void split2h(float v, __half& h, __half& l) {
    h = __float2half_rn(v);
    l = __float2half_rn(v - __half2float(h));
}
__device__ __forceinline__ uint32_t packh2(__half a, __half b) {
    __half2 t = __halves2half2(a, b);
    return *reinterpret_cast<uint32_t*>(&t);
}
__device__ __forceinline__ float gelu_f(float v) {
    return 0.5f * v * (1.0f + erff(v * 0.70710678118654752f));
}
__device__ __forceinline__ uint32_t smem_u32(const void* p) {
    uint32_t a;
    asm("{ .reg .u64 t; cvta.to.shared.u64 t, %1; cvt.u32.u64 %0, t; }" : "=r"(a) : "l"(p));
    return a;
}

#define LDSM_X4(r, addr) \
    asm volatile("ldmatrix.sync.aligned.m8n8.x4.shared.b16 {%0,%1,%2,%3}, [%4];" \
        : "=r"((r)[0]), "=r"((r)[1]), "=r"((r)[2]), "=r"((r)[3]) : "r"(addr))
#define LDSM_X2(r, addr) \
    asm volatile("ldmatrix.sync.aligned.m8n8.x2.shared.b16 {%0,%1}, [%2];" \
        : "=r"((r)[0]), "=r"((r)[1]) : "r"(addr))
#define MMA16816H(c, a, b) \
    asm volatile("mma.sync.aligned.m16n8k16.row.col.f32.f16.f16.f32 " \
        "{%0,%1,%2,%3}, {%4,%5,%6,%7}, {%8,%9}, {%0,%1,%2,%3};" \
        : "+f"((c)[0]), "+f"((c)[1]), "+f"((c)[2]), "+f"((c)[3]) \
        : "r"((a)[0]), "r"((a)[1]), "r"((a)[2]), "r"((a)[3]), "r"((b)[0]), "r"((b)[1]))

// swizzled byte offset within a 128-row x 128B tile
__device__ __forceinline__ uint32_t swz(uint32_t row, uint32_t seg) {
    return row * 128u + ((seg ^ (row & 7u)) * 16u);
}

// ---------------- fused router + x split (fp16 hi/lo) ----------------
__global__ __launch_bounds__(256) void router_split_kernel(
        const float* __restrict__ x,
        const float* __restrict__ rw,
        const float* __restrict__ rb) {
    __shared__ float s_rw[DIM * 9];          // [k*9 + e]
    const int tid = threadIdx.x, lane = tid & 31, wid = tid >> 5;
    for (int i = tid; i < DIM * NEXP; i += 256) {
        int k = i >> 3, e = i & 7;
        s_rw[k * 9 + e] = rw[i];
    }
    __syncthreads();

    const int n = blockIdx.x * 8 + wid;
    const float* xr = x + (size_t)n * DIM;
    float acc[NEXP];
#pragma unroll
    for (int e = 0; e < NEXP; e++) acc[e] = 0.f;

#pragma unroll 4
    for (int i = 0; i < 16; i++) {
        const int k = i * 64 + lane * 2;
        float2 v = *(const float2*)(xr + k);
        __half h0, l0, h1, l1;
        split2h(v.x, h0, l0); split2h(v.y, h1, l1);
        *(uint32_t*)(g_xh + (size_t)n * DIM + k) = packh2(h0, h1);
        *(uint32_t*)(g_xl + (size_t)n * DIM + k) = packh2(l0, l1);
        const float* r0 = s_rw + k * 9;
        const float* r1 = s_rw + (k + 1) * 9;
#pragma unroll
        for (int e = 0; e < NEXP; e++) acc[e] += v.x * r0[e] + v.y * r1[e];
    }
#pragma unroll
    for (int off = 16; off > 0; off >>= 1)
#pragma unroll
        for (int e = 0; e < NEXP; e++)
            acc[e] += __shfl_xor_sync(0xFFFFFFFFu, acc[e], off);

    if (lane == 0) {
        float l[NEXP];
#pragma unroll
        for (int e = 0; e < NEXP; e++) l[e] = acc[e] + rb[e];
        float m = l[0];
#pragma unroll
        for (int e = 1; e < NEXP; e++) m = fmaxf(m, l[e]);
        float p[NEXP], sum = 0.f;
#pragma unroll
        for (int e = 0; e < NEXP; e++) { p[e] = expf(l[e] - m); sum += p[e]; }
#pragma unroll
        for (int e = 0; e < NEXP; e++) p[e] /= sum;
        int i0 = 0;
        for (int e = 1; e < NEXP; e++) if (p[e] > p[i0]) i0 = e;
        int i1 = (i0 == 0) ? 1 : 0;
        for (int e = 0; e < NEXP; e++) if (e != i0 && p[e] > p[i1]) i1 = e;
        float s2 = p[i0] + p[i1];
        g_topi[n * 2 + 0] = i0;  g_topi[n * 2 + 1] = i1;
        g_topw[n * 2 + 0] = p[i0] / s2;  g_topw[n * 2 + 1] = p[i1] / s2;
    }
}

// ---------------- fused corr + dispatch build (ONE block, 1024 threads) ----------------
__global__ __launch_bounds__(1024) void dispatch_kernel() {
    __shared__ float s_wred[32][16];
    __shared__ float s_corr[16];
    __shared__ int   s_cnt[NEXP];
    const int tid = threadIdx.x, lane = tid & 31, wid = tid >> 5;

    float a[16];
#pragma unroll
    for (int q = 0; q < 16; q++) a[q] = 0.f;
    for (int i = tid; i < NTOK; i += 1024) {
        int e0 = g_topi[i * 2 + 0], e1 = g_topi[i * 2 + 1];
        float w0 = g_topw[i * 2 + 0], w1 = g_topw[i * 2 + 1];
#pragma unroll
        for (int e = 0; e < NEXP; e++) {
            a[e * 2 + 0] += (e0 == e) ? w0 : 0.f;
            a[e * 2 + 1] += (e1 == e) ? w1 : 0.f;
        }
    }
#pragma unroll
    for (int off = 16; off > 0; off >>= 1)
#pragma unroll
        for (int q = 0; q < 16; q++)
            a[q] += __shfl_xor_sync(0xFFFFFFFFu, a[q], off);
    if (lane == 0)
#pragma unroll
        for (int q = 0; q < 16; q++) s_wred[wid][q] = a[q];
    if (tid < NEXP) s_cnt[tid] = 0;
    __syncthreads();
    if (tid < 16) {
        float s = 0.f;
        for (int w = 0; w < 32; w++) s += s_wred[w][tid];
        s_corr[tid] = s;
    }
    __syncthreads();

    for (int n = tid; n < NTOK; n += 1024) {
        int ee[4]; float ww[4]; int ne = 2;
        ee[0] = g_topi[n * 2 + 0]; ww[0] = g_topw[n * 2 + 0];
        ee[1] = g_topi[n * 2 + 1]; ww[1] = g_topw[n * 2 + 1];
        if (n < NEXP) {
#pragma unroll
            for (int j = 0; j < 2; j++) {
                float c = s_corr[n * 2 + j];
                int f = -1;
                for (int s = 0; s < ne; s++) if (ee[s] == j) f = s;
                if (f >= 0) ww[f] += c;
                else if (c != 0.0f) { ee[ne] = j; ww[ne] = c; ne++; }
            }
        }
        g_nent[n] = ne;
        for (int s = 0; s < ne; s++) {
            float w = fminf(ww[s], CAPACITY);
            int e = ee[s];
            int idx = atomicAdd(&s_cnt[e], 1);
            g_ptok[e * PMAX + idx] = n;
            g_pslot[e * PMAX + idx] = s;
            g_pw[e * PMAX + idx] = w;
        }
    }
    __syncthreads();
    if (tid < NEXP) g_cnt[tid] = s_cnt[tid];
}

// ---------------- prep: transpose weights  w[e][k][n] -> [e][n][k] single fp16 ----------------
__global__ void tsplit_kernel(const float* __restrict__ w, int which, int R, int C) {
    __shared__ float t[32][33];
    __half* oh = which ? g_w2 : g_w1;
    int e = blockIdx.z;
    int k0 = blockIdx.y * 32, n0 = blockIdx.x * 32;
    int tx = threadIdx.x, ty = threadIdx.y;
    const float* wp = w + (size_t)e * R * C;
#pragma unroll
    for (int r = 0; r < 32; r += 8)
        t[ty + r][tx] = wp[(size_t)(k0 + ty + r) * C + n0 + tx];
    __syncthreads();
#pragma unroll
    for (int r = 0; r < 32; r += 8) {
        float v = t[tx][ty + r];
        size_t o = ((size_t)e * C + n0 + ty + r) * R + k0 + tx;
        oh[o] = __float2half_rn(v);
    }
}

// ---------------- GEMM mainloop ----------------
__device__ __forceinline__ void load_stage(char* smem, uint32_t sb, int tid, int c) {
    const __half* const* s_ptr = (const __half* const*)smem;     // 384 entries
    const int* s_pred = (const int*)(smem + 3072);               // 128 entries
    const int kel = c * KC;
    const uint32_t sbase = sb + HDR + (uint32_t)((c & 1) * STAGE_B);
#pragma unroll
    for (int it = 0; it < 12; it++) {
        const int id = tid + it * 256;
        const int region = id >> 10, within = id & 1023;
        const int row = within >> 3, seg = within & 7;
        const char* src = (const char*)(s_ptr[region * 128 + row] + kel) + seg * 16;
        uint32_t dst = sbase + (uint32_t)(region * SPLIT_B) + swz(row, seg);
        int sz = (region < 2) ? s_pred[row] : 16;
        asm volatile("cp.async.cg.shared.global [%0], [%1], 16, %2;"
                     :: "r"(dst), "l"(src), "r"(sz) : "memory");
    }
    asm volatile("cp.async.commit_group;" ::: "memory");
}

__device__ __forceinline__ void compute_stage(uint32_t sb, int tid, int buf, float acc[4][4][4]) {
    const int lane = tid & 31, wid = tid >> 5;
    const int wr = wid >> 2, wc = wid & 3;
    const uint32_t base = sb + HDR + (uint32_t)(buf * STAGE_B);
    const uint32_t arow = wr * 64 + (lane & 15);
    const uint32_t asegbit = (lane >> 4) & 1;          // col 0 / col 8
    const uint32_t brow = wc * 32 + (lane & 7);
    const uint32_t bsegbit = (lane >> 3) & 1;
#pragma unroll
    for (int kst = 0; kst < 4; kst++) {
        const uint32_t aseg = kst * 2 + asegbit;
        const uint32_t bseg = kst * 2 + bsegbit;
        uint32_t ah[4][4], al[4][4], bh[4][2];
#pragma unroll
        for (int mt = 0; mt < 4; mt++) {
            uint32_t r = arow + mt * 16;
            uint32_t addr = base + swz(r, aseg);
            LDSM_X4(ah[mt], addr);
            LDSM_X4(al[mt], addr + SPLIT_B);
        }
#pragma unroll
        for (int nt = 0; nt < 4; nt++) {
            uint32_t r = brow + nt * 8;
            LDSM_X2(bh[nt], base + 2 * SPLIT_B + swz(r, bseg));
        }
#pragma unroll
        for (int mt = 0; mt < 4; mt++)
#pragma unroll
            for (int nt = 0; nt < 4; nt++) {
                MMA16816H(acc[mt][nt], ah[mt], bh[nt]);
                MMA16816H(acc[mt][nt], al[mt], bh[nt]);
            }
    }
}

__device__ __forceinline__ void gemm_mainloop(char* smem, uint32_t sb, int tid, float acc[4][4][4]) {
#pragma unroll
    for (int mt = 0; mt < 4; mt++)
#pragma unroll
        for (int nt = 0; nt < 4; nt++)
#pragma unroll
            for (int i = 0; i < 4; i++) acc[mt][nt][i] = 0.f;
    load_stage(smem, sb, tid, 0);
#pragma unroll 1
    for (int c = 0; c < NCHUNK; c++) {
        if (c + 1 < NCHUNK) {
            load_stage(smem, sb, tid, c + 1);
            asm volatile("cp.async.wait_group 1;" ::: "memory");
        } else {
            asm volatile("cp.async.wait_group 0;" ::: "memory");
        }
        __syncthreads();
        compute_stage(sb, tid, c & 1, acc);
        __syncthreads();
    }
}

// ---------------- GEMM1: y1 = gelu(w * (x @ W1) + b1) -> fp16 hi/lo ----------------
__global__ __launch_bounds__(256, 2) void gemm1_tc(const float* __restrict__ b1) {
    const int e = blockIdx.z;
    const int M = g_cnt[e];
    const int m0 = blockIdx.y * 128;
    if (m0 >= M) return;
    const int n0 = blockIdx.x * 128;
    extern __shared__ char smem[];
    const uint32_t sb = smem_u32(smem);
    const int tid = threadIdx.x;

    {
        const __half** s_ptr = (const __half**)smem;
        int* s_pred = (int*)(smem + 3072);
        if (tid < 128) {
            int p = m0 + tid;
            bool v = p < M;
            int tok = v ? g_ptok[e * PMAX + p] : 0;
            s_ptr[0 * 128 + tid] = g_xh + (size_t)tok * DIM;
            s_ptr[1 * 128 + tid] = g_xl + (size_t)tok * DIM;
            s_ptr[2 * 128 + tid] = g_w1 + ((size_t)e * HID + n0 + tid) * DIM;
            s_pred[tid] = v ? 16 : 0;
        }
    }
    __syncthreads();

    float acc[4][4][4];
    gemm_mainloop(smem, sb, tid, acc);

    const int lane = tid & 31, wid = tid >> 5;
    const int wr = wid >> 2, wc = wid & 3;
    const int gid = lane >> 2, tig = lane & 3;
    const float* b1e = b1 + e * HID + n0 + wc * 32;
#pragma unroll
    for (int mt = 0; mt < 4; mt++) {
        const int p0 = m0 + wr * 64 + mt * 16 + gid;
        const int p1 = p0 + 8;
        const bool v0 = p0 < M, v1 = p1 < M;
        const float w0 = v0 ? g_pw[e * PMAX + p0] : 0.f;
        const float w1 = v1 ? g_pw[e * PMAX + p1] : 0.f;
        __half* oh0 = g_y1h + ((size_t)(e * PMAX + p0)) * HID + n0 + wc * 32;
        __half* ol0 = g_y1l + ((size_t)(e * PMAX + p0)) * HID + n0 + wc * 32;
        __half* oh1 = g_y1h + ((size_t)(e * PMAX + p1)) * HID + n0 + wc * 32;
        __half* ol1 = g_y1l + ((size_t)(e * PMAX + p1)) * HID + n0 + wc * 32;
#pragma unroll
        for (int nt = 0; nt < 4; nt++) {
            const int co = nt * 8 + 2 * tig;
            const float* c = acc[mt][nt];
            if (v0) {
                float t0 = gelu_f(w0 * c[0] + b1e[co]);
                float t1 = gelu_f(w0 * c[1] + b1e[co + 1]);
                __half h0, l0, h1, l1;
                split2h(t0, h0, l0); split2h(t1, h1, l1);
                *(uint32_t*)(oh0 + co) = packh2(h0, h1);
                *(uint32_t*)(ol0 + co) = packh2(l0, l1);
            }
            if (v1) {
                float t0 = gelu_f(w1 * c[2] + b1e[co]);
                float t1 = gelu_f(w1 * c[3] + b1e[co + 1]);
                __half h0, l0, h1, l1;
                split2h(t0, h0, l0); split2h(t1, h1, l1);
                *(uint32_t*)(oh1 + co) = packh2(h0, h1);
                *(uint32_t*)(ol1 + co) = packh2(l0, l1);
            }
        }
    }
}

// ---------------- GEMM2: pout = w * (y1 @ W2 + b2) ----------------
__global__ __launch_bounds__(256, 2) void gemm2_tc(const float* __restrict__ b2) {
    const int e = blockIdx.z;
    const int M = g_cnt[e];
    const int m0 = blockIdx.y * 128;
    if (m0 >= M) return;
    const int n0 = blockIdx.x * 128;
    extern __shared__ char smem[];
    const uint32_t sb = smem_u32(smem);
    const int tid = threadIdx.x;

    {
        const __half** s_ptr = (const __half**)smem;
        int* s_pred = (int*)(smem + 3072);
        if (tid < 128) {
            int p = m0 + tid;
            bool v = p < M;
            size_t ar = ((size_t)(e * PMAX + (v ? p : 0))) * HID;
            s_ptr[0 * 128 + tid] = g_y1h + ar;
            s_ptr[1 * 128 + tid] = g_y1l + ar;
            s_ptr[2 * 128 + tid] = g_w2 + ((size_t)e * DIM + n0 + tid) * HID;
            s_pred[tid] = v ? 16 : 0;
        }
    }
    __syncthreads();

    float acc[4][4][4];
    gemm_mainloop(smem, sb, tid, acc);

    const int lane = tid & 31, wid = tid >> 5;
    const int wr = wid >> 2, wc = wid & 3;
    const int gid = lane >> 2, tig = lane & 3;
    const float* b2e = b2 + e * DIM + n0 + wc * 32;
#pragma unroll
    for (int mt = 0; mt < 4; mt++) {
        const int p0 = m0 + wr * 64 + mt * 16 + gid;
        const int p1 = p0 + 8;
        const bool v0 = p0 < M, v1 = p1 < M;
        int tok0 = 0, slot0 = 0, tok1 = 0, slot1 = 0;
        float w0 = 0.f, w1 = 0.f;
        if (v0) { tok0 = g_ptok[e * PMAX + p0]; slot0 = g_pslot[e * PMAX + p0]; w0 = g_pw[e * PMAX + p0]; }
        if (v1) { tok1 = g_ptok[e * PMAX + p1]; slot1 = g_pslot[e * PMAX + p1]; w1 = g_pw[e * PMAX + p1]; }
        float* d0 = g_pout + ((size_t)(tok0 * 4 + slot0)) * DIM + n0 + wc * 32;
        float* d1 = g_pout + ((size_t)(tok1 * 4 + slot1)) * DIM + n0 + wc * 32;
#pragma unroll
        for (int nt = 0; nt < 4; nt++) {
            const int co = nt * 8 + 2 * tig;
            const float* c = acc[mt][nt];
            if (v0) *(float2*)(d0 + co) = make_float2(w0 * (c[0] + b2e[co]), w0 * (c[1] + b2e[co + 1]));
            if (v1) *(float2*)(d1 + co) = make_float2(w1 * (c[2] + b2e[co]), w1 * (c[3] + b2e[co + 1]));
        }
    }
}

// ---------------- combine ----------------
__global__ void combine_kernel(float* __restrict__ out) {
    const int n = blockIdx.x, tid = threadIdx.x;
    const int ne = g_nent[n];
    const int d = tid * 4;
    float4 s = make_float4(0.f, 0.f, 0.f, 0.f);
    for (int sl = 0; sl < ne; sl++) {
        float4 v = *(const float4*)(g_pout + ((size_t)(n * 4 + sl)) * DIM + d);
        s.x += v.x; s.y += v.y; s.z += v.z; s.w += v.w;
    }
    *(float4*)(out + (size_t)n * DIM + d) = s;
}

// ---------------- launch ----------------
extern "C" void kernel_launch(void* const* d_in, const int* in_sizes, int n_in,
                              void* d_out, int out_size) {
    const float* x  = (const float*)d_in[0];
    const float* rw = (const float*)d_in[1];
    const float* rb = (const float*)d_in[2];
    const float* w1 = (const float*)d_in[3];
    const float* b1 = (const float*)d_in[4];
    const float* w2 = (const float*)d_in[5];
    const float* b2 = (const float*)d_in[6];
    float* out = (float*)d_out;

    cudaFuncSetAttribute(gemm1_tc, cudaFuncAttributeMaxDynamicSharedMemorySize, SMEM_GEMM);
    cudaFuncSetAttribute(gemm2_tc, cudaFuncAttributeMaxDynamicSharedMemorySize, SMEM_GEMM);

    dim3 gg(HID / 128, PMAX / 128, NEXP);    // (8, 65, 8); dead tiles exit at top
    dim3 tg(DIM / 32, HID / 32, NEXP);

    // order chosen so gemm1_tc is launch index 3 (the one ncu captures)
    router_split_kernel<<<NTOK / 8, 256>>>(x, rw, rb);        // 0
    dispatch_kernel<<<1, 1024>>>();                            // 1
    tsplit_kernel<<<tg, dim3(32, 8)>>>(w1, 0, DIM, HID);       // 2
    gemm1_tc<<<gg, 256, SMEM_GEMM>>>(b1);                      // 3  <- profiled
    tsplit_kernel<<<tg, dim3(32, 8)>>>(w2, 1, HID, DIM);       // 4
    gemm2_tc<<<gg, 256, SMEM_GEMM>>>(b2);                      // 5
    combine_kernel<<<NTOK, 256>>>(out);                        // 6
}

// round 11
// speedup vs baseline: 5.5867x; 1.4415x over previous
#include <cuda_runtime.h>
#include <cuda_fp16.h>
#include <math.h>
#include <stdint.h>

#define NTOK 8192
#define DIM  1024
#define NEXP 8
#define HID  1024
#define PMAX 8320
#define CAPACITY 1280.0f

#define KC     64            // K elements per pipeline stage (fp16: 128B rows)
#define NCHUNK 16            // 1024 / 64
#define NSTAGE 3
#define ROWB   128
#define SPLIT_B (128 * ROWB)       // 16384 B: one 128x64 fp16 tile
#define STAGE_B (2 * SPLIT_B)      // A, B = 32768
#define HDR     4096               // 256 src ptrs (2KB) + 128 pred ints
#define SMEM_GEMM (HDR + NSTAGE * STAGE_B)   // 102400 -> 2 CTAs/SM

// ---------------- scratch globals ----------------
__device__ int   g_topi[NTOK * 2];
__device__ float g_topw[NTOK * 2];
__device__ int   g_nent[NTOK];
__device__ int   g_cnt[NEXP];
__device__ int   g_ptok[NEXP * PMAX];
__device__ int   g_pslot[NEXP * PMAX];
__device__ float g_pw[NEXP * PMAX];
__device__ __align__(256) __half g_xh[(size_t)NTOK * DIM];
__device__ __align__(256) __half g_w1[(size_t)NEXP * HID * DIM];   // [e][n][k] fp16
__device__ __align__(256) __half g_w2[(size_t)NEXP * DIM * HID];   // [e][n][k] fp16
__device__ __align__(256) __half g_y1h[(size_t)NEXP * PMAX * HID];
__device__ float g_pout[(size_t)NTOK * 4 * DIM];

// ---------------- small helpers ----------------
__device__ __forceinline__ uint32_t packh2(__half a, __half b) {
    __half2 t = __halves2half2(a, b);
    return *reinterpret_cast<uint32_t*>(&t);
}
__device__ __forceinline__ float gelu_f(float v) {
    return 0.5f * v * (1.0f + erff(v * 0.70710678118654752f));
}
__device__ __forceinline__ uint32_t smem_u32(const void* p) {
    uint32_t a;
    asm("{ .reg .u64 t; cvta.to.shared.u64 t, %1; cvt.u32.u64 %0, t; }" : "=r"(a) : "l"(p));
    return a;
}

#define LDSM_X4(r, addr) \
    asm volatile("ldmatrix.sync.aligned.m8n8.x4.shared.b16 {%0,%1,%2,%3}, [%4];" \
        : "=r"((r)[0]), "=r"((r)[1]), "=r"((r)[2]), "=r"((r)[3]) : "r"(addr))
#define MMA16816H(c, a, b) \
    asm volatile("mma.sync.aligned.m16n8k16.row.col.f32.f16.f16.f32 " \
        "{%0,%1,%2,%3}, {%4,%5,%6,%7}, {%8,%9}, {%0,%1,%2,%3};" \
        : "+f"((c)[0]), "+f"((c)[1]), "+f"((c)[2]), "+f"((c)[3]) \
        : "r"((a)[0]), "r"((a)[1]), "r"((a)[2]), "r"((a)[3]), "r"((b)[0]), "r"((b)[1]))

// swizzled byte offset within a 128-row x 128B tile
__device__ __forceinline__ uint32_t swz(uint32_t row, uint32_t seg) {
    return row * 128u + ((seg ^ (row & 7u)) * 16u);
}

// ---------------- fused router + x->fp16 ----------------
__global__ __launch_bounds__(256) void router_split_kernel(
        const float* __restrict__ x,
        const float* __restrict__ rw,
        const float* __restrict__ rb) {
    __shared__ float s_rw[DIM * 9];          // [k*9 + e]
    const int tid = threadIdx.x, lane = tid & 31, wid = tid >> 5;
    for (int i = tid; i < DIM * NEXP; i += 256) {
        int k = i >> 3, e = i & 7;
        s_rw[k * 9 + e] = rw[i];
    }
    __syncthreads();

    const int n = blockIdx.x * 8 + wid;
    const float* xr = x + (size_t)n * DIM;
    float acc[NEXP];
#pragma unroll
    for (int e = 0; e < NEXP; e++) acc[e] = 0.f;

#pragma unroll 4
    for (int i = 0; i < 16; i++) {
        const int k = i * 64 + lane * 2;
        float2 v = *(const float2*)(xr + k);
        *(uint32_t*)(g_xh + (size_t)n * DIM + k) =
            packh2(__float2half_rn(v.x), __float2half_rn(v.y));
        const float* r0 = s_rw + k * 9;
        const float* r1 = s_rw + (k + 1) * 9;
#pragma unroll
        for (int e = 0; e < NEXP; e++) acc[e] += v.x * r0[e] + v.y * r1[e];
    }
#pragma unroll
    for (int off = 16; off > 0; off >>= 1)
#pragma unroll
        for (int e = 0; e < NEXP; e++)
            acc[e] += __shfl_xor_sync(0xFFFFFFFFu, acc[e], off);

    if (lane == 0) {
        float l[NEXP];
#pragma unroll
        for (int e = 0; e < NEXP; e++) l[e] = acc[e] + rb[e];
        float m = l[0];
#pragma unroll
        for (int e = 1; e < NEXP; e++) m = fmaxf(m, l[e]);
        float p[NEXP], sum = 0.f;
#pragma unroll
        for (int e = 0; e < NEXP; e++) { p[e] = expf(l[e] - m); sum += p[e]; }
#pragma unroll
        for (int e = 0; e < NEXP; e++) p[e] /= sum;
        int i0 = 0;
        for (int e = 1; e < NEXP; e++) if (p[e] > p[i0]) i0 = e;
        int i1 = (i0 == 0) ? 1 : 0;
        for (int e = 0; e < NEXP; e++) if (e != i0 && p[e] > p[i1]) i1 = e;
        float s2 = p[i0] + p[i1];
        g_topi[n * 2 + 0] = i0;  g_topi[n * 2 + 1] = i1;
        g_topw[n * 2 + 0] = p[i0] / s2;  g_topw[n * 2 + 1] = p[i1] / s2;
    }
}

// ---------------- fused corr + dispatch build (ONE block, 1024 threads) ----------------
__global__ __launch_bounds__(1024) void dispatch_kernel() {
    __shared__ float s_wred[32][16];
    __shared__ float s_corr[16];
    __shared__ int   s_cnt[NEXP];
    const int tid = threadIdx.x, lane = tid & 31, wid = tid >> 5;

    float a[16];
#pragma unroll
    for (int q = 0; q < 16; q++) a[q] = 0.f;
    for (int i = tid; i < NTOK; i += 1024) {
        int e0 = g_topi[i * 2 + 0], e1 = g_topi[i * 2 + 1];
        float w0 = g_topw[i * 2 + 0], w1 = g_topw[i * 2 + 1];
#pragma unroll
        for (int e = 0; e < NEXP; e++) {
            a[e * 2 + 0] += (e0 == e) ? w0 : 0.f;
            a[e * 2 + 1] += (e1 == e) ? w1 : 0.f;
        }
    }
#pragma unroll
    for (int off = 16; off > 0; off >>= 1)
#pragma unroll
        for (int q = 0; q < 16; q++)
            a[q] += __shfl_xor_sync(0xFFFFFFFFu, a[q], off);
    if (lane == 0)
#pragma unroll
        for (int q = 0; q < 16; q++) s_wred[wid][q] = a[q];
    if (tid < NEXP) s_cnt[tid] = 0;
    __syncthreads();
    if (tid < 16) {
        float s = 0.f;
        for (int w = 0; w < 32; w++) s += s_wred[w][tid];
        s_corr[tid] = s;
    }
    __syncthreads();

    for (int n = tid; n < NTOK; n += 1024) {
        int ee[4]; float ww[4]; int ne = 2;
        ee[0] = g_topi[n * 2 + 0]; ww[0] = g_topw[n * 2 + 0];
        ee[1] = g_topi[n * 2 + 1]; ww[1] = g_topw[n * 2 + 1];
        if (n < NEXP) {
#pragma unroll
            for (int j = 0; j < 2; j++) {
                float c = s_corr[n * 2 + j];
                int f = -1;
                for (int s = 0; s < ne; s++) if (ee[s] == j) f = s;
                if (f >= 0) ww[f] += c;
                else if (c != 0.0f) { ee[ne] = j; ww[ne] = c; ne++; }
            }
        }
        g_nent[n] = ne;
        for (int s = 0; s < ne; s++) {
            float w = fminf(ww[s], CAPACITY);
            int e = ee[s];
            int idx = atomicAdd(&s_cnt[e], 1);
            g_ptok[e * PMAX + idx] = n;
            g_pslot[e * PMAX + idx] = s;
            g_pw[e * PMAX + idx] = w;
        }
    }
    __syncthreads();
    if (tid < NEXP) g_cnt[tid] = s_cnt[tid];
}

// ---------------- prep: transpose weights  w[e][k][n] -> [e][n][k] fp16 ----------------
__global__ void tsplit_kernel(const float* __restrict__ w, int which, int R, int C) {
    __shared__ float t[32][33];
    __half* oh = which ? g_w2 : g_w1;
    int e = blockIdx.z;
    int k0 = blockIdx.y * 32, n0 = blockIdx.x * 32;
    int tx = threadIdx.x, ty = threadIdx.y;
    const float* wp = w + (size_t)e * R * C;
#pragma unroll
    for (int r = 0; r < 32; r += 8)
        t[ty + r][tx] = wp[(size_t)(k0 + ty + r) * C + n0 + tx];
    __syncthreads();
#pragma unroll
    for (int r = 0; r < 32; r += 8) {
        float v = t[tx][ty + r];
        size_t o = ((size_t)e * C + n0 + ty + r) * R + k0 + tx;
        oh[o] = __float2half_rn(v);
    }
}

// ---------------- GEMM mainloop ----------------
__device__ __forceinline__ void load_stage(char* smem, uint32_t sb, int tid, int c) {
    const __half* const* s_ptr = (const __half* const*)smem;     // 256 entries
    const int* s_pred = (const int*)(smem + 2048);               // 128 entries
    const int kel = c * KC;
    const uint32_t sbase = sb + HDR + (uint32_t)((c % NSTAGE) * STAGE_B);
#pragma unroll
    for (int it = 0; it < 8; it++) {
        const int id = tid + it * 256;
        const int region = id >> 10, within = id & 1023;
        const int row = within >> 3, seg = within & 7;
        const char* src = (const char*)(s_ptr[region * 128 + row] + kel) + seg * 16;
        uint32_t dst = sbase + (uint32_t)(region * SPLIT_B) + swz(row, seg);
        int sz = (region == 0) ? s_pred[row] : 16;
        asm volatile("cp.async.cg.shared.global [%0], [%1], 16, %2;"
                     :: "r"(dst), "l"(src), "r"(sz) : "memory");
    }
    asm volatile("cp.async.commit_group;" ::: "memory");
}

__device__ __forceinline__ void compute_stage(uint32_t sb, int tid, int buf, float acc[4][4][4]) {
    const int lane = tid & 31, wid = tid >> 5;
    const int wr = wid >> 2, wc = wid & 3;
    const uint32_t base = sb + HDR + (uint32_t)(buf * STAGE_B);
    const uint32_t arow = wr * 64 + (lane & 15);
    const uint32_t asegbit = (lane >> 4) & 1;
    // B x4: lanes 0-7 rows, 8-15 same rows seg+1, 16-23 rows+8, 24-31 rows+8 seg+1
    const uint32_t brow = wc * 32 + ((lane >> 4) & 1) * 8 + (lane & 7);
    const uint32_t bsegbit = (lane >> 3) & 1;
#pragma unroll
    for (int kst = 0; kst < 4; kst++) {
        const uint32_t aseg = kst * 2 + asegbit;
        const uint32_t bseg = kst * 2 + bsegbit;
        uint32_t ah[4][4], bb[2][4];
#pragma unroll
        for (int mt = 0; mt < 4; mt++)
            LDSM_X4(ah[mt], base + swz(arow + mt * 16, aseg));
#pragma unroll
        for (int bt = 0; bt < 2; bt++)
            LDSM_X4(bb[bt], base + SPLIT_B + swz(brow + bt * 16, bseg));
#pragma unroll
        for (int mt = 0; mt < 4; mt++)
#pragma unroll
            for (int nt = 0; nt < 4; nt++)
                MMA16816H(acc[mt][nt], ah[mt], &bb[nt >> 1][(nt & 1) * 2]);
    }
}

__device__ __forceinline__ void gemm_mainloop(char* smem, uint32_t sb, int tid, float acc[4][4][4]) {
#pragma unroll
    for (int mt = 0; mt < 4; mt++)
#pragma unroll
        for (int nt = 0; nt < 4; nt++)
#pragma unroll
            for (int i = 0; i < 4; i++) acc[mt][nt][i] = 0.f;
    load_stage(smem, sb, tid, 0);
    load_stage(smem, sb, tid, 1);
    load_stage(smem, sb, tid, 2);
#pragma unroll 1
    for (int c = 0; c < NCHUNK; c++) {
        if (c <= NCHUNK - 3)      asm volatile("cp.async.wait_group 2;" ::: "memory");
        else if (c == NCHUNK - 2) asm volatile("cp.async.wait_group 1;" ::: "memory");
        else                      asm volatile("cp.async.wait_group 0;" ::: "memory");
        __syncthreads();
        compute_stage(sb, tid, c % NSTAGE, acc);
        __syncthreads();
        if (c + 3 < NCHUNK) load_stage(smem, sb, tid, c + 3);
    }
}

// ---------------- GEMM1: y1 = gelu(w * (x @ W1) + b1) -> fp16 ----------------
__global__ __launch_bounds__(256, 2) void gemm1_tc(const float* __restrict__ b1) {
    const int e = blockIdx.z;
    const int M = g_cnt[e];
    const int m0 = blockIdx.y * 128;
    if (m0 >= M) return;
    const int n0 = blockIdx.x * 128;
    extern __shared__ char smem[];
    const uint32_t sb = smem_u32(smem);
    const int tid = threadIdx.x;

    {
        const __half** s_ptr = (const __half**)smem;
        int* s_pred = (int*)(smem + 2048);
        if (tid < 128) {
            int p = m0 + tid;
            bool v = p < M;
            int tok = v ? g_ptok[e * PMAX + p] : 0;
            s_ptr[0 * 128 + tid] = g_xh + (size_t)tok * DIM;
            s_ptr[1 * 128 + tid] = g_w1 + ((size_t)e * HID + n0 + tid) * DIM;
            s_pred[tid] = v ? 16 : 0;
        }
    }
    __syncthreads();

    float acc[4][4][4];
    gemm_mainloop(smem, sb, tid, acc);

    const int lane = tid & 31, wid = tid >> 5;
    const int wr = wid >> 2, wc = wid & 3;
    const int gid = lane >> 2, tig = lane & 3;
    const float* b1e = b1 + e * HID + n0 + wc * 32;
#pragma unroll
    for (int mt = 0; mt < 4; mt++) {
        const int p0 = m0 + wr * 64 + mt * 16 + gid;
        const int p1 = p0 + 8;
        const bool v0 = p0 < M, v1 = p1 < M;
        const float w0 = v0 ? g_pw[e * PMAX + p0] : 0.f;
        const float w1 = v1 ? g_pw[e * PMAX + p1] : 0.f;
        __half* oh0 = g_y1h + ((size_t)(e * PMAX + p0)) * HID + n0 + wc * 32;
        __half* oh1 = g_y1h + ((size_t)(e * PMAX + p1)) * HID + n0 + wc * 32;
#pragma unroll
        for (int nt = 0; nt < 4; nt++) {
            const int co = nt * 8 + 2 * tig;
            const float* c = acc[mt][nt];
            if (v0) {
                float t0 = gelu_f(w0 * c[0] + b1e[co]);
                float t1 = gelu_f(w0 * c[1] + b1e[co + 1]);
                *(uint32_t*)(oh0 + co) = packh2(__float2half_rn(t0), __float2half_rn(t1));
            }
            if (v1) {
                float t0 = gelu_f(w1 * c[2] + b1e[co]);
                float t1 = gelu_f(w1 * c[3] + b1e[co + 1]);
                *(uint32_t*)(oh1 + co) = packh2(__float2half_rn(t0), __float2half_rn(t1));
            }
        }
    }
}

// ---------------- GEMM2: pout = w * (y1 @ W2 + b2) ----------------
__global__ __launch_bounds__(256, 2) void gemm2_tc(const float* __restrict__ b2) {
    const int e = blockIdx.z;
    const int M = g_cnt[e];
    const int m0 = blockIdx.y * 128;
    if (m0 >= M) return;
    const int n0 = blockIdx.x * 128;
    extern __shared__ char smem[];
    const uint32_t sb = smem_u32(smem);
    const int tid = threadIdx.x;

    {
        const __half** s_ptr = (const __half**)smem;
        int* s_pred = (int*)(smem + 2048);
        if (tid < 128) {
            int p = m0 + tid;
            bool v = p < M;
            size_t ar = ((size_t)(e * PMAX + (v ? p : 0))) * HID;
            s_ptr[0 * 128 + tid] = g_y1h + ar;
            s_ptr[1 * 128 + tid] = g_w2 + ((size_t)e * DIM + n0 + tid) * HID;
            s_pred[tid] = v ? 16 : 0;
        }
    }
    __syncthreads();

    float acc[4][4][4];
    gemm_mainloop(smem, sb, tid, acc);

    const int lane = tid & 31, wid = tid >> 5;
    const int wr = wid >> 2, wc = wid & 3;
    const int gid = lane >> 2, tig = lane & 3;
    const float* b2e = b2 + e * DIM + n0 + wc * 32;
#pragma unroll
    for (int mt = 0; mt < 4; mt++) {
        const int p0 = m0 + wr * 64 + mt * 16 + gid;
        const int p1 = p0 + 8;
        const bool v0 = p0 < M, v1 = p1 < M;
        int tok0 = 0, slot0 = 0, tok1 = 0, slot1 = 0;
        float w0 = 0.f, w1 = 0.f;
        if (v0) { tok0 = g_ptok[e * PMAX + p0]; slot0 = g_pslot[e * PMAX + p0]; w0 = g_pw[e * PMAX + p0]; }
        if (v1) { tok1 = g_ptok[e * PMAX + p1]; slot1 = g_pslot[e * PMAX + p1]; w1 = g_pw[e * PMAX + p1]; }
        float* d0 = g_pout + ((size_t)(tok0 * 4 + slot0)) * DIM + n0 + wc * 32;
        float* d1 = g_pout + ((size_t)(tok1 * 4 + slot1)) * DIM + n0 + wc * 32;
#pragma unroll
        for (int nt = 0; nt < 4; nt++) {
            const int co = nt * 8 + 2 * tig;
            const float* c = acc[mt][nt];
            if (v0) *(float2*)(d0 + co) = make_float2(w0 * (c[0] + b2e[co]), w0 * (c[1] + b2e[co + 1]));
            if (v1) *(float2*)(d1 + co) = make_float2(w1 * (c[2] + b2e[co]), w1 * (c[3] + b2e[co + 1]));
        }
    }
}

// ---------------- combine ----------------
__global__ void combine_kernel(float* __restrict__ out) {
    const int n = blockIdx.x, tid = threadIdx.x;
    const int ne = g_nent[n];
    const int d = tid * 4;
    float4 s = make_float4(0.f, 0.f, 0.f, 0.f);
    for (int sl = 0; sl < ne; sl++) {
        float4 v = *(const float4*)(g_pout + ((size_t)(n * 4 + sl)) * DIM + d);
        s.x += v.x; s.y += v.y; s.z += v.z; s.w += v.w;
    }
    *(float4*)(out + (size_t)n * DIM + d) = s;
}

// ---------------- launch ----------------
extern "C" void kernel_launch(void* const* d_in, const int* in_sizes, int n_in,
                              void* d_out, int out_size) {
    const float* x  = (const float*)d_in[0];
    const float* rw = (const float*)d_in[1];
    const float* rb = (const float*)d_in[2];
    const float* w1 = (const float*)d_in[3];
    const float* b1 = (const float*)d_in[4];
    const float* w2 = (const float*)d_in[5];
    const float* b2 = (const float*)d_in[6];
    float* out = (float*)d_out;

    cudaFuncSetAttribute(gemm1_tc, cudaFuncAttributeMaxDynamicSharedMemorySize, SMEM_GEMM);
    cudaFuncSetAttribute(gemm2_tc, cudaFuncAttributeMaxDynamicSharedMemorySize, SMEM_GEMM);

    dim3 gg(HID / 128, PMAX / 128, NEXP);    // (8, 65, 8); dead tiles exit at top
    dim3 tg(DIM / 32, HID / 32, NEXP);

    // order chosen so gemm1_tc is launch index 3 (the one ncu captures)
    router_split_kernel<<<NTOK / 8, 256>>>(x, rw, rb);        // 0
    dispatch_kernel<<<1, 1024>>>();                            // 1
    tsplit_kernel<<<tg, dim3(32, 8)>>>(w1, 0, DIM, HID);       // 2
    gemm1_tc<<<gg, 256, SMEM_GEMM>>>(b1);                      // 3  <- profiled
    tsplit_kernel<<<tg, dim3(32, 8)>>>(w2, 1, HID, DIM);       // 4
    gemm2_tc<<<gg, 256, SMEM_GEMM>>>(b2);                      // 5
    combine_kernel<<<NTOK, 256>>>(out);                        // 6
}

// round 13
// speedup vs baseline: 5.7202x; 1.0239x over previous
#include <cuda_runtime.h>
#include <cuda_fp16.h>
#include <math.h>
#include <stdint.h>

#define NTOK 8192
#define DIM  1024
#define NEXP 8
#define HID  1024
#define PMAX 8320
#define CAPACITY 1280.0f

#define KC     64            // K elements per pipeline stage (fp16: 128B rows)
#define NCHUNK 16            // 1024 / 64
#define NSTAGE 3
#define ROWB   128
#define SPLIT_B (128 * ROWB)       // 16384 B: one 128x64 fp16 tile
#define STAGE_B (2 * SPLIT_B)      // A, B = 32768
#define HDR     4096               // 256 src ptrs (2KB) + 128 pred ints
#define SMEM_GEMM (HDR + NSTAGE * STAGE_B)   // 102400 -> 2 CTAs/SM

// ---------------- scratch globals ----------------
__device__ int   g_topi[NTOK * 2];
__device__ float g_topw[NTOK * 2];
__device__ int   g_nent[NTOK];
__device__ int   g_cnt[NEXP];
__device__ int   g_ptok[NEXP * PMAX];
__device__ int   g_pslot[NEXP * PMAX];
__device__ float g_pw[NEXP * PMAX];
__device__ __align__(256) __half g_xh[(size_t)NTOK * DIM];
__device__ __align__(256) __half g_w1[(size_t)NEXP * HID * DIM];   // [e][n][k] fp16
__device__ __align__(256) __half g_w2[(size_t)NEXP * DIM * HID];   // [e][n][k] fp16
__device__ __align__(256) __half g_y1h[(size_t)NEXP * PMAX * HID];
__device__ float g_pout[(size_t)NTOK * 4 * DIM];

// ---------------- small helpers ----------------
__device__ __forceinline__ uint32_t packh2(__half a, __half b) {
    __half2 t = __halves2half2(a, b);
    return *reinterpret_cast<uint32_t*>(&t);
}
__device__ __forceinline__ float gelu_f(float v) {
    return 0.5f * v * (1.0f + erff(v * 0.70710678118654752f));
}
__device__ __forceinline__ uint32_t smem_u32(const void* p) {
    uint32_t a;
    asm("{ .reg .u64 t; cvta.to.shared.u64 t, %1; cvt.u32.u64 %0, t; }" : "=r"(a) : "l"(p));
    return a;
}

#define LDSM_X4(r, addr) \
    asm volatile("ldmatrix.sync.aligned.m8n8.x4.shared.b16 {%0,%1,%2,%3}, [%4];" \
        : "=r"((r)[0]), "=r"((r)[1]), "=r"((r)[2]), "=r"((r)[3]) : "r"(addr))
#define MMA16816H(c, a, b) \
    asm volatile("mma.sync.aligned.m16n8k16.row.col.f32.f16.f16.f32 " \
        "{%0,%1,%2,%3}, {%4,%5,%6,%7}, {%8,%9}, {%0,%1,%2,%3};" \
        : "+f"((c)[0]), "+f"((c)[1]), "+f"((c)[2]), "+f"((c)[3]) \
        : "r"((a)[0]), "r"((a)[1]), "r"((a)[2]), "r"((a)[3]), "r"((b)[0]), "r"((b)[1]))

// swizzled byte offset within a 128-row x 128B tile
__device__ __forceinline__ uint32_t swz(uint32_t row, uint32_t seg) {
    return row * 128u + ((seg ^ (row & 7u)) * 16u);
}

// ---------------- fused router + x->fp16 ----------------
__global__ __launch_bounds__(256) void router_split_kernel(
        const float* __restrict__ x,
        const float* __restrict__ rw,
        const float* __restrict__ rb) {
    __shared__ float s_rw[DIM * 9];          // [k*9 + e]
    const int tid = threadIdx.x, lane = tid & 31, wid = tid >> 5;
    for (int i = tid; i < DIM * NEXP; i += 256) {
        int k = i >> 3, e = i & 7;
        s_rw[k * 9 + e] = rw[i];
    }
    __syncthreads();

    const int n = blockIdx.x * 8 + wid;
    const float* xr = x + (size_t)n * DIM;
    float acc[NEXP];
#pragma unroll
    for (int e = 0; e < NEXP; e++) acc[e] = 0.f;

#pragma unroll 4
    for (int i = 0; i < 16; i++) {
        const int k = i * 64 + lane * 2;
        float2 v = *(const float2*)(xr + k);
        *(uint32_t*)(g_xh + (size_t)n * DIM + k) =
            packh2(__float2half_rn(v.x), __float2half_rn(v.y));
        const float* r0 = s_rw + k * 9;
        const float* r1 = s_rw + (k + 1) * 9;
#pragma unroll
        for (int e = 0; e < NEXP; e++) acc[e] += v.x * r0[e] + v.y * r1[e];
    }
#pragma unroll
    for (int off = 16; off > 0; off >>= 1)
#pragma unroll
        for (int e = 0; e < NEXP; e++)
            acc[e] += __shfl_xor_sync(0xFFFFFFFFu, acc[e], off);

    if (lane == 0) {
        float l[NEXP];
#pragma unroll
        for (int e = 0; e < NEXP; e++) l[e] = acc[e] + rb[e];
        float m = l[0];
#pragma unroll
        for (int e = 1; e < NEXP; e++) m = fmaxf(m, l[e]);
        float p[NEXP], sum = 0.f;
#pragma unroll
        for (int e = 0; e < NEXP; e++) { p[e] = expf(l[e] - m); sum += p[e]; }
#pragma unroll
        for (int e = 0; e < NEXP; e++) p[e] /= sum;
        int i0 = 0;
        for (int e = 1; e < NEXP; e++) if (p[e] > p[i0]) i0 = e;
        int i1 = (i0 == 0) ? 1 : 0;
        for (int e = 0; e < NEXP; e++) if (e != i0 && p[e] > p[i1]) i1 = e;
        float s2 = p[i0] + p[i1];
        g_topi[n * 2 + 0] = i0;  g_topi[n * 2 + 1] = i1;
        g_topw[n * 2 + 0] = p[i0] / s2;  g_topw[n * 2 + 1] = p[i1] / s2;
    }
}

// ---------------- fused corr + dispatch build (ONE block, 1024 threads) ----------------
__global__ __launch_bounds__(1024) void dispatch_kernel() {
    __shared__ float s_wred[32][16];
    __shared__ float s_corr[16];
    __shared__ int   s_cnt[NEXP];
    const int tid = threadIdx.x, lane = tid & 31, wid = tid >> 5;

    float a[16];
#pragma unroll
    for (int q = 0; q < 16; q++) a[q] = 0.f;
    for (int i = tid; i < NTOK; i += 1024) {
        int e0 = g_topi[i * 2 + 0], e1 = g_topi[i * 2 + 1];
        float w0 = g_topw[i * 2 + 0], w1 = g_topw[i * 2 + 1];
#pragma unroll
        for (int e = 0; e < NEXP; e++) {
            a[e * 2 + 0] += (e0 == e) ? w0 : 0.f;
            a[e * 2 + 1] += (e1 == e) ? w1 : 0.f;
        }
    }
#pragma unroll
    for (int off = 16; off > 0; off >>= 1)
#pragma unroll
        for (int q = 0; q < 16; q++)
            a[q] += __shfl_xor_sync(0xFFFFFFFFu, a[q], off);
    if (lane == 0)
#pragma unroll
        for (int q = 0; q < 16; q++) s_wred[wid][q] = a[q];
    if (tid < NEXP) s_cnt[tid] = 0;
    __syncthreads();
    if (tid < 16) {
        float s = 0.f;
        for (int w = 0; w < 32; w++) s += s_wred[w][tid];
        s_corr[tid] = s;
    }
    __syncthreads();

    for (int n = tid; n < NTOK; n += 1024) {
        int ee[4]; float ww[4]; int ne = 2;
        ee[0] = g_topi[n * 2 + 0]; ww[0] = g_topw[n * 2 + 0];
        ee[1] = g_topi[n * 2 + 1]; ww[1] = g_topw[n * 2 + 1];
        if (n < NEXP) {
#pragma unroll
            for (int j = 0; j < 2; j++) {
                float c = s_corr[n * 2 + j];
                int f = -1;
                for (int s = 0; s < ne; s++) if (ee[s] == j) f = s;
                if (f >= 0) ww[f] += c;
                else if (c != 0.0f) { ee[ne] = j; ww[ne] = c; ne++; }
            }
        }
        g_nent[n] = ne;
        for (int s = 0; s < ne; s++) {
            float w = fminf(ww[s], CAPACITY);
            int e = ee[s];
            int idx = atomicAdd(&s_cnt[e], 1);
            g_ptok[e * PMAX + idx] = n;
            g_pslot[e * PMAX + idx] = s;
            g_pw[e * PMAX + idx] = w;
        }
    }
    __syncthreads();
    if (tid < NEXP) g_cnt[tid] = s_cnt[tid];
}

// ---------------- prep: transpose BOTH weights  w[e][k][n] -> [e][n][k] fp16 ----------------
// grid.z: 0-7 -> w1 expert z, 8-15 -> w2 expert z-8. Both are 1024x1024 per expert.
__global__ void tsplit_kernel(const float* __restrict__ w1s, const float* __restrict__ w2s) {
    __shared__ float t[32][33];
    const int z = blockIdx.z;
    const int e = z & 7;
    const float* w = (z < 8) ? w1s : w2s;
    __half* oh = (z < 8) ? g_w1 : g_w2;
    int k0 = blockIdx.y * 32, n0 = blockIdx.x * 32;
    int tx = threadIdx.x, ty = threadIdx.y;
    const float* wp = w + (size_t)e * DIM * HID;
#pragma unroll
    for (int r = 0; r < 32; r += 8)
        t[ty + r][tx] = wp[(size_t)(k0 + ty + r) * HID + n0 + tx];
    __syncthreads();
#pragma unroll
    for (int r = 0; r < 32; r += 8) {
        float v = t[tx][ty + r];
        size_t o = ((size_t)e * HID + n0 + ty + r) * DIM + k0 + tx;
        oh[o] = __float2half_rn(v);
    }
}

// ---------------- GEMM mainloop ----------------
__device__ __forceinline__ void load_stage(char* smem, uint32_t sb, int tid, int c) {
    const __half* const* s_ptr = (const __half* const*)smem;     // 256 entries
    const int* s_pred = (const int*)(smem + 2048);               // 128 entries
    const int kel = c * KC;
    const uint32_t sbase = sb + HDR + (uint32_t)((c % NSTAGE) * STAGE_B);
#pragma unroll
    for (int it = 0; it < 8; it++) {
        const int id = tid + it * 256;
        const int region = id >> 10, within = id & 1023;
        const int row = within >> 3, seg = within & 7;
        const char* src = (const char*)(s_ptr[region * 128 + row] + kel) + seg * 16;
        uint32_t dst = sbase + (uint32_t)(region * SPLIT_B) + swz(row, seg);
        int sz = (region == 0) ? s_pred[row] : 16;
        asm volatile("cp.async.cg.shared.global [%0], [%1], 16, %2;"
                     :: "r"(dst), "l"(src), "r"(sz) : "memory");
    }
    asm volatile("cp.async.commit_group;" ::: "memory");
}

__device__ __forceinline__ void compute_stage(uint32_t sb, int tid, int buf, float acc[4][4][4]) {
    const int lane = tid & 31, wid = tid >> 5;
    const int wr = wid >> 2, wc = wid & 3;
    const uint32_t base = sb + HDR + (uint32_t)(buf * STAGE_B);
    const uint32_t arow = wr * 64 + (lane & 15);
    const uint32_t asegbit = (lane >> 4) & 1;
    const uint32_t brow = wc * 32 + ((lane >> 4) & 1) * 8 + (lane & 7);
    const uint32_t bsegbit = (lane >> 3) & 1;
#pragma unroll
    for (int kst = 0; kst < 4; kst++) {
        const uint32_t aseg = kst * 2 + asegbit;
        const uint32_t bseg = kst * 2 + bsegbit;
        uint32_t ah[4][4], bb[2][4];
        // interleaved: first MMA's operands load first
        LDSM_X4(ah[0], base + swz(arow, aseg));
        LDSM_X4(bb[0], base + SPLIT_B + swz(brow, bseg));
        LDSM_X4(bb[1], base + SPLIT_B + swz(brow + 16, bseg));
        LDSM_X4(ah[1], base + swz(arow + 16, aseg));
        LDSM_X4(ah[2], base + swz(arow + 32, aseg));
        LDSM_X4(ah[3], base + swz(arow + 48, aseg));
#pragma unroll
        for (int mt = 0; mt < 4; mt++)
#pragma unroll
            for (int nt = 0; nt < 4; nt++)
                MMA16816H(acc[mt][nt], ah[mt], &bb[nt >> 1][(nt & 1) * 2]);
    }
}

__device__ __forceinline__ void gemm_mainloop(char* smem, uint32_t sb, int tid, float acc[4][4][4]) {
#pragma unroll
    for (int mt = 0; mt < 4; mt++)
#pragma unroll
        for (int nt = 0; nt < 4; nt++)
#pragma unroll
            for (int i = 0; i < 4; i++) acc[mt][nt][i] = 0.f;
    load_stage(smem, sb, tid, 0);
    load_stage(smem, sb, tid, 1);
#pragma unroll 1
    for (int c = 0; c < NCHUNK; c++) {
        if (c == NCHUNK - 1) asm volatile("cp.async.wait_group 0;" ::: "memory");
        else                 asm volatile("cp.async.wait_group 1;" ::: "memory");
        __syncthreads();   // c's data visible to all; all done reading buffer (c+2)%3
        if (c + 2 < NCHUNK) load_stage(smem, sb, tid, c + 2);
        compute_stage(sb, tid, c % NSTAGE, acc);
    }
}

// ---------------- GEMM1: y1 = gelu(w * (x @ W1) + b1) -> fp16 ----------------
__global__ __launch_bounds__(256, 2) void gemm1_tc(const float* __restrict__ b1) {
    const int e = blockIdx.z;
    const int M = g_cnt[e];
    const int m0 = blockIdx.y * 128;
    if (m0 >= M) return;
    const int n0 = blockIdx.x * 128;
    extern __shared__ char smem[];
    const uint32_t sb = smem_u32(smem);
    const int tid = threadIdx.x;

    {
        const __half** s_ptr = (const __half**)smem;
        int* s_pred = (int*)(smem + 2048);
        if (tid < 128) {
            int p = m0 + tid;
            bool v = p < M;
            int tok = v ? g_ptok[e * PMAX + p] : 0;
            s_ptr[0 * 128 + tid] = g_xh + (size_t)tok * DIM;
            s_ptr[1 * 128 + tid] = g_w1 + ((size_t)e * HID + n0 + tid) * DIM;
            s_pred[tid] = v ? 16 : 0;
        }
    }
    __syncthreads();

    float acc[4][4][4];
    gemm_mainloop(smem, sb, tid, acc);

    const int lane = tid & 31, wid = tid >> 5;
    const int wr = wid >> 2, wc = wid & 3;
    const int gid = lane >> 2, tig = lane & 3;
    const float* b1e = b1 + e * HID + n0 + wc * 32;
#pragma unroll
    for (int mt = 0; mt < 4; mt++) {
        const int p0 = m0 + wr * 64 + mt * 16 + gid;
        const int p1 = p0 + 8;
        const bool v0 = p0 < M, v1 = p1 < M;
        const float w0 = v0 ? g_pw[e * PMAX + p0] : 0.f;
        const float w1 = v1 ? g_pw[e * PMAX + p1] : 0.f;
        __half* oh0 = g_y1h + ((size_t)(e * PMAX + p0)) * HID + n0 + wc * 32;
        __half* oh1 = g_y1h + ((size_t)(e * PMAX + p1)) * HID + n0 + wc * 32;
#pragma unroll
        for (int nt = 0; nt < 4; nt++) {
            const int co = nt * 8 + 2 * tig;
            const float* c = acc[mt][nt];
            if (v0) {
                float t0 = gelu_f(w0 * c[0] + b1e[co]);
                float t1 = gelu_f(w0 * c[1] + b1e[co + 1]);
                *(uint32_t*)(oh0 + co) = packh2(__float2half_rn(t0), __float2half_rn(t1));
            }
            if (v1) {
                float t0 = gelu_f(w1 * c[2] + b1e[co]);
                float t1 = gelu_f(w1 * c[3] + b1e[co + 1]);
                *(uint32_t*)(oh1 + co) = packh2(__float2half_rn(t0), __float2half_rn(t1));
            }
        }
    }
}

// ---------------- GEMM2: pout = w * (y1 @ W2 + b2) ----------------
__global__ __launch_bounds__(256, 2) void gemm2_tc(const float* __restrict__ b2) {
    const int e = blockIdx.z;
    const int M = g_cnt[e];
    const int m0 = blockIdx.y * 128;
    if (m0 >= M) return;
    const int n0 = blockIdx.x * 128;
    extern __shared__ char smem[];
    const uint32_t sb = smem_u32(smem);
    const int tid = threadIdx.x;

    {
        const __half** s_ptr = (const __half**)smem;
        int* s_pred = (int*)(smem + 2048);
        if (tid < 128) {
            int p = m0 + tid;
            bool v = p < M;
            size_t ar = ((size_t)(e * PMAX + (v ? p : 0))) * HID;
            s_ptr[0 * 128 + tid] = g_y1h + ar;
            s_ptr[1 * 128 + tid] = g_w2 + ((size_t)e * DIM + n0 + tid) * HID;
            s_pred[tid] = v ? 16 : 0;
        }
    }
    __syncthreads();

    float acc[4][4][4];
    gemm_mainloop(smem, sb, tid, acc);

    const int lane = tid & 31, wid = tid >> 5;
    const int wr = wid >> 2, wc = wid & 3;
    const int gid = lane >> 2, tig = lane & 3;
    const float* b2e = b2 + e * DIM + n0 + wc * 32;
#pragma unroll
    for (int mt = 0; mt < 4; mt++) {
        const int p0 = m0 + wr * 64 + mt * 16 + gid;
        const int p1 = p0 + 8;
        const bool v0 = p0 < M, v1 = p1 < M;
        int tok0 = 0, slot0 = 0, tok1 = 0, slot1 = 0;
        float w0 = 0.f, w1 = 0.f;
        if (v0) { tok0 = g_ptok[e * PMAX + p0]; slot0 = g_pslot[e * PMAX + p0]; w0 = g_pw[e * PMAX + p0]; }
        if (v1) { tok1 = g_ptok[e * PMAX + p1]; slot1 = g_pslot[e * PMAX + p1]; w1 = g_pw[e * PMAX + p1]; }
        float* d0 = g_pout + ((size_t)(tok0 * 4 + slot0)) * DIM + n0 + wc * 32;
        float* d1 = g_pout + ((size_t)(tok1 * 4 + slot1)) * DIM + n0 + wc * 32;
#pragma unroll
        for (int nt = 0; nt < 4; nt++) {
            const int co = nt * 8 + 2 * tig;
            const float* c = acc[mt][nt];
            if (v0) *(float2*)(d0 + co) = make_float2(w0 * (c[0] + b2e[co]), w0 * (c[1] + b2e[co + 1]));
            if (v1) *(float2*)(d1 + co) = make_float2(w1 * (c[2] + b2e[co]), w1 * (c[3] + b2e[co + 1]));
        }
    }
}

// ---------------- combine ----------------
__global__ void combine_kernel(float* __restrict__ out) {
    const int n = blockIdx.x, tid = threadIdx.x;
    const int ne = g_nent[n];
    const int d = tid * 4;
    float4 s = make_float4(0.f, 0.f, 0.f, 0.f);
    for (int sl = 0; sl < ne; sl++) {
        float4 v = *(const float4*)(g_pout + ((size_t)(n * 4 + sl)) * DIM + d);
        s.x += v.x; s.y += v.y; s.z += v.z; s.w += v.w;
    }
    *(float4*)(out + (size_t)n * DIM + d) = s;
}

// ---------------- launch ----------------
extern "C" void kernel_launch(void* const* d_in, const int* in_sizes, int n_in,
                              void* d_out, int out_size) {
    const float* x  = (const float*)d_in[0];
    const float* rw = (const float*)d_in[1];
    const float* rb = (const float*)d_in[2];
    const float* w1 = (const float*)d_in[3];
    const float* b1 = (const float*)d_in[4];
    const float* w2 = (const float*)d_in[5];
    const float* b2 = (const float*)d_in[6];
    float* out = (float*)d_out;

    cudaFuncSetAttribute(gemm1_tc, cudaFuncAttributeMaxDynamicSharedMemorySize, SMEM_GEMM);
    cudaFuncSetAttribute(gemm2_tc, cudaFuncAttributeMaxDynamicSharedMemorySize, SMEM_GEMM);

    dim3 gg(HID / 128, PMAX / 128, NEXP);    // (8, 65, 8); dead tiles exit at top
    dim3 tg(DIM / 32, HID / 32, NEXP * 2);   // both weights in one launch

    // order chosen so gemm1_tc is launch index 3 (the one ncu captures)
    router_split_kernel<<<NTOK / 8, 256>>>(x, rw, rb);        // 0
    dispatch_kernel<<<1, 1024>>>();                            // 1
    tsplit_kernel<<<tg, dim3(32, 8)>>>(w1, w2);                // 2
    gemm1_tc<<<gg, 256, SMEM_GEMM>>>(b1);                      // 3  <- profiled
    gemm2_tc<<<gg, 256, SMEM_GEMM>>>(b2);                      // 4
    combine_kernel<<<NTOK, 256>>>(out);                        // 5
}